// round 3
// baseline (speedup 1.0000x reference)
#include <cuda_runtime.h>
#include <math.h>

// Problem constants
#define H      2560
#define ESZ    2048
#define EPER   512
#define IPER   128
#define NB     64
#define NT     32
#define INSZ   128
#define NIN_ROWS 640
#define KP     16         // K-split slots per h-tile (contiguous chunk ranges)

// Scratch (device globals: allocation-free rule)
__device__ float g_WeffT[H * H];                // |W_rec|*mask, TRANSPOSED: [k][h]
__device__ float g_P[KP * H * NB];              // K-split partials [slot][h][b]
__device__ float g_Iin[NT * NIN_ROWS * NB];     // precomputed input drive [t][h'][b]
__device__ float g_state[H * NB];               // state, [h][b]
__device__ float g_actT[H * NB];                // retanh(state_t), [h][b]

__device__ __forceinline__ int area_of(int u) {
    return u < ESZ ? (u >> 9) : ((u - ESZ) >> 7);
}

union UF2 { unsigned long long u; float2 f; };

__device__ __forceinline__ void ffma2(unsigned long long& d,
                                      unsigned long long a,
                                      unsigned long long b) {
    asm("fma.rn.f32x2 %0, %1, %2, %0;" : "+l"(d) : "l"(a), "l"(b));
}
__device__ __forceinline__ unsigned long long dup2(float w) {
    unsigned long long r;
    asm("mov.b64 %0, {%1, %1};" : "=l"(r) : "r"(__float_as_uint(w)));
    return r;
}

// ---------------------------------------------------------------------------
// Prep 1: WeffT[k][h] = |W_rec[h][k]| * sign(k) * conn(h,k), diag 0.
// ---------------------------------------------------------------------------
__global__ void prep_weights(const float* __restrict__ Wrec) {
    __shared__ float tS[32][33];
    int h0 = blockIdx.x * 32, k0 = blockIdx.y * 32;
    int tid = threadIdx.x;                 // 128 threads
    for (int r = 0; r < 8; ++r) {
        int flat = tid + r * 128;
        int i = flat >> 5, kk = flat & 31;
        int h = h0 + i, k = k0 + kk;
        int ar = area_of(h);
        int conn; float sgn;
        if (k < ESZ) { int d = ar - (k >> 9); conn = (d >= -1 && d <= 1); sgn = 1.0f; }
        else         { conn = ((k - ESZ) >> 7) == ar;                     sgn = -1.0f; }
        float m = (conn && (h != k)) ? sgn : 0.0f;
        tS[kk][i] = fabsf(Wrec[h * H + k]) * m;
    }
    __syncthreads();
    for (int r = 0; r < 8; ++r) {
        int flat = tid + r * 128;
        int kk = flat >> 5, i = flat & 31;
        g_WeffT[(k0 + kk) * H + h0 + i] = tS[kk][i];
    }
}

// ---------------------------------------------------------------------------
// Prep 2: state [h][b] + initial activation [h][b]
// ---------------------------------------------------------------------------
__global__ void prep_state(const float* __restrict__ state0) {
    int idx = blockIdx.x * blockDim.x + threadIdx.x;
    if (idx >= NB * H) return;
    int b = idx / H, h = idx % H;
    float s = state0[idx];
    g_state[h * NB + b] = s;
    g_actT[h * NB + b] = tanhf(fmaxf(s, 0.0f));
}

// ---------------------------------------------------------------------------
// Prep 3: input drive for all timesteps (area-0 rows only)
// ---------------------------------------------------------------------------
__global__ void prep_input(const float* __restrict__ x, const float* __restrict__ Win) {
    int t   = blockIdx.y;
    int hp0 = blockIdx.x * 16;
    __shared__ float xS[64 * 133];
    __shared__ float wS[16 * 128];

    for (int r = threadIdx.x; r < 64 * 128; r += blockDim.x) {
        int bb = r >> 7, kk = r & 127;
        xS[bb * 133 + kk] = fmaxf(x[t * (NB * INSZ) + r], 0.0f);
    }
    for (int r = threadIdx.x; r < 16 * 128; r += blockDim.x) {
        int i = r >> 7, kk = r & 127;
        int hp = hp0 + i;
        int h  = (hp < EPER) ? hp : (ESZ + (hp - EPER));
        wS[r] = fabsf(Win[h * INSZ + kk]);
    }
    __syncthreads();

    int b  = threadIdx.x & 63;
    int hq = threadIdx.x >> 6;
    float acc[4] = {0.f, 0.f, 0.f, 0.f};
    for (int k = 0; k < 128; ++k) {
        float xv = xS[b * 133 + k];
#pragma unroll
        for (int j = 0; j < 4; ++j)
            acc[j] = fmaf(xv, wS[(hq * 4 + j) * 128 + k], acc[j]);
    }
#pragma unroll
    for (int j = 0; j < 4; ++j)
        g_Iin[(t * NIN_ROWS + hp0 + hq * 4 + j) * NB + b] = acc[j];
}

// ---------------------------------------------------------------------------
// Step kernel A: block-sparse partial GEMM with packed f32x2 FMA.
//   Tile: 64h x 64b, 128 threads, 4h x 8b per thread.
//   grid = (H/64=40, KP=16); slot s handles contiguous chunk range
//   [s*nch/KP, (s+1)*nch/KP) of this tile's K-chunks (32 k each).
// ---------------------------------------------------------------------------
__global__ void __launch_bounds__(128) step_partial() {
    const int h0 = blockIdx.x * 64;
    const int s  = blockIdx.y;
    const int area = area_of(h0);
    const int aE0 = (area > 0 ? area - 1 : 0);
    const int aE1 = (area < 3 ? area + 1 : 3);
    const int k0E = aE0 * EPER;
    const int lenE = (aE1 - aE0 + 1) * EPER;
    const int k0I = ESZ + area * IPER;
    const int nch = (lenE + IPER) >> 5;     // 36 or 52 chunks of 32

    const int cb = (s * nch) / KP;
    const int ce = ((s + 1) * nch) / KP;

    __shared__ float actS[32 * 64];         // [k][b]
    __shared__ float wS[32 * 64];           // [k][h_local]

    const int tid = threadIdx.x;
    const int tx = tid & 7;                 // b-group (8 b each)
    const int ty = tid >> 3;                // h-group (4 h each), 0..15

    unsigned actS_u = (unsigned)__cvta_generic_to_shared(actS);
    unsigned wS_u   = (unsigned)__cvta_generic_to_shared(wS);

    unsigned long long acc[4][4];
#pragma unroll
    for (int j = 0; j < 4; ++j)
#pragma unroll
        for (int p = 0; p < 4; ++p) acc[j][p] = 0ull;

    float4 pa[4], pw[4];

    // prefetch first chunk
    {
        int off = cb * 32;
        int kg = (off < lenE) ? (k0E + off) : (k0I + (off - lenE));
        const float4* asrc = reinterpret_cast<const float4*>(g_actT + kg * 64);
#pragma unroll
        for (int r = 0; r < 4; ++r) pa[r] = asrc[tid + r * 128];
#pragma unroll
        for (int r = 0; r < 4; ++r) {
            int idx = tid + r * 128;
            int kk = idx >> 4, i2 = idx & 15;
            pw[r] = *reinterpret_cast<const float4*>(g_WeffT + (kg + kk) * H + h0 + i2 * 4);
        }
    }

    for (int c = cb; c < ce; ++c) {
        // stage prefetched chunk
#pragma unroll
        for (int r = 0; r < 4; ++r)
            reinterpret_cast<float4*>(actS)[tid + r * 128] = pa[r];
#pragma unroll
        for (int r = 0; r < 4; ++r) {
            int idx = tid + r * 128;
            int kk = idx >> 4, i2 = idx & 15;
            *reinterpret_cast<float4*>(wS + kk * 64 + i2 * 4) = pw[r];
        }
        __syncthreads();

        // prefetch next chunk (overlaps with compute)
        if (c + 1 < ce) {
            int off = (c + 1) * 32;
            int kg = (off < lenE) ? (k0E + off) : (k0I + (off - lenE));
            const float4* asrc = reinterpret_cast<const float4*>(g_actT + kg * 64);
#pragma unroll
            for (int r = 0; r < 4; ++r) pa[r] = asrc[tid + r * 128];
#pragma unroll
            for (int r = 0; r < 4; ++r) {
                int idx = tid + r * 128;
                int kk = idx >> 4, i2 = idx & 15;
                pw[r] = *reinterpret_cast<const float4*>(g_WeffT + (kg + kk) * H + h0 + i2 * 4);
            }
        }

        // compute: 32 k of 4h x 8b with FFMA2
#pragma unroll
        for (int k = 0; k < 32; ++k) {
            unsigned long long a0, a1, a2, a3;
            unsigned aaddr = actS_u + k * 256 + tx * 32;
            asm volatile("ld.shared.v2.b64 {%0,%1}, [%2];"
                         : "=l"(a0), "=l"(a1) : "r"(aaddr));
            asm volatile("ld.shared.v2.b64 {%0,%1}, [%2+16];"
                         : "=l"(a2), "=l"(a3) : "r"(aaddr));
            float4 w4;
            unsigned waddr = wS_u + k * 256 + ty * 16;
            asm volatile("ld.shared.v4.f32 {%0,%1,%2,%3}, [%4];"
                         : "=f"(w4.x), "=f"(w4.y), "=f"(w4.z), "=f"(w4.w) : "r"(waddr));
            unsigned long long w0 = dup2(w4.x), w1 = dup2(w4.y),
                               w2 = dup2(w4.z), w3 = dup2(w4.w);
            ffma2(acc[0][0], a0, w0); ffma2(acc[0][1], a1, w0);
            ffma2(acc[0][2], a2, w0); ffma2(acc[0][3], a3, w0);
            ffma2(acc[1][0], a0, w1); ffma2(acc[1][1], a1, w1);
            ffma2(acc[1][2], a2, w1); ffma2(acc[1][3], a3, w1);
            ffma2(acc[2][0], a0, w2); ffma2(acc[2][1], a1, w2);
            ffma2(acc[2][2], a2, w2); ffma2(acc[2][3], a3, w2);
            ffma2(acc[3][0], a0, w3); ffma2(acc[3][1], a1, w3);
            ffma2(acc[3][2], a2, w3); ffma2(acc[3][3], a3, w3);
        }
        __syncthreads();
    }

    // write partials: P[s][h][b], 8 consecutive b per thread
#pragma unroll
    for (int j = 0; j < 4; ++j) {
        int h = h0 + ty * 4 + j;
        UF2 u0, u1, u2, u3;
        u0.u = acc[j][0]; u1.u = acc[j][1]; u2.u = acc[j][2]; u3.u = acc[j][3];
        float* dst = g_P + (s * H + h) * NB + tx * 8;
        *reinterpret_cast<float4*>(dst)     = make_float4(u0.f.x, u0.f.y, u1.f.x, u1.f.y);
        *reinterpret_cast<float4*>(dst + 4) = make_float4(u2.f.x, u2.f.y, u3.f.x, u3.f.y);
    }
}

// ---------------------------------------------------------------------------
// Step kernel B: reduce KP partials + bias + input, leaky update, retanh.
// Writes g_state [h][b], g_actT [h][b], out[t][b][h].
// ---------------------------------------------------------------------------
__global__ void step_update(const float* __restrict__ b_rec, float* __restrict__ out, int t) {
    int h0 = blockIdx.x * 16;
    bool hasIn = (h0 < EPER) || (h0 >= ESZ && h0 < ESZ + IPER);
    int b  = threadIdx.x & 63;
    int hq = threadIdx.x >> 6;
    __shared__ float outS[16 * 65];

#pragma unroll
    for (int j = 0; j < 4; ++j) {
        int hl = hq * 4 + j;
        int h  = h0 + hl;
        float p = 0.f;
#pragma unroll
        for (int kp = 0; kp < KP; ++kp)
            p += g_P[(kp * H + h) * NB + b];
        p += b_rec[h];
        if (hasIn) {
            int hp = (h < EPER) ? h : (EPER + (h - ESZ));
            p += g_Iin[(t * NIN_ROWS + hp) * NB + b];
        }
        float s  = g_state[h * NB + b];
        float ns = s * 0.8f + 0.2f * p;
        g_state[h * NB + b] = ns;
        float a = tanhf(fmaxf(ns, 0.0f));
        g_actT[h * NB + b] = a;
        outS[hl * 65 + b] = a;
    }
    __syncthreads();

    int b2 = threadIdx.x >> 2;
    int jq = threadIdx.x & 3;
    float4 v;
    v.x = outS[(jq * 4 + 0) * 65 + b2];
    v.y = outS[(jq * 4 + 1) * 65 + b2];
    v.z = outS[(jq * 4 + 2) * 65 + b2];
    v.w = outS[(jq * 4 + 3) * 65 + b2];
    *reinterpret_cast<float4*>(&out[(t * NB + b2) * H + h0 + jq * 4]) = v;
}

// ---------------------------------------------------------------------------
extern "C" void kernel_launch(void* const* d_in, const int* in_sizes, int n_in,
                              void* d_out, int out_size) {
    (void)in_sizes; (void)n_in; (void)out_size;
    const float* x      = (const float*)d_in[0];
    const float* W_in   = (const float*)d_in[1];
    const float* W_rec  = (const float*)d_in[2];
    const float* b_rec  = (const float*)d_in[3];
    const float* state0 = (const float*)d_in[4];
    float* out = (float*)d_out;

    prep_weights<<<dim3(H / 32, H / 32), 128>>>(W_rec);
    prep_state<<<(NB * H + 255) / 256, 256>>>(state0);
    prep_input<<<dim3(NIN_ROWS / 16, NT), 256>>>(x, W_in);

    for (int t = 0; t < NT; ++t) {
        step_partial<<<dim3(H / 64, KP), 128>>>();
        step_update<<<H / 16, 256>>>(b_rec, out, t);
    }
}

// round 4
// speedup vs baseline: 1.0574x; 1.0574x over previous
#include <cuda_runtime.h>
#include <math.h>

// Problem constants
#define H      2560
#define ESZ    2048
#define EPER   512
#define IPER   128
#define NB     64
#define NT     32
#define INSZ   128
#define NIN_ROWS 640
#define NTILE  20          // h-tiles of 128
#define NSLOT  300         // total (tile, slot) CTAs per step

// Static schedule: 36-chunk tiles get 12 slots, 52-chunk tiles get 18.
__constant__ int cS[NTILE]    = {12,12,12,12, 18,18,18,18, 18,18,18,18, 12,12,12,12, 12,18,18,12};
__constant__ int cBase[NTILE] = {0,12,24,36, 48,66,84,102, 120,138,156,174, 192,204,216,228, 240,252,270,288};
__constant__ int cArea[NTILE] = {0,0,0,0, 1,1,1,1, 2,2,2,2, 3,3,3,3, 0,1,2,3};

// Scratch (device globals: allocation-free rule)
__device__ float g_WeffT[H * H];                // |W_rec|*mask, TRANSPOSED: [k][h]
__device__ float g_P[NSLOT * 128 * NB];         // partials [globalSlot][h_local(128)][b]
__device__ float g_Iin[NT * NIN_ROWS * NB];     // precomputed input drive [t][h'][b]
__device__ float g_state[H * NB];               // state, [h][b]
__device__ float g_actT[H * NB];                // retanh(state_t), [h][b]

__device__ __forceinline__ int area_of(int u) {
    return u < ESZ ? (u >> 9) : ((u - ESZ) >> 7);
}

union UF2 { unsigned long long u; float2 f; };

__device__ __forceinline__ void ffma2(unsigned long long& d,
                                      unsigned long long a,
                                      unsigned long long b) {
    asm("fma.rn.f32x2 %0, %1, %2, %0;" : "+l"(d) : "l"(a), "l"(b));
}
__device__ __forceinline__ unsigned long long dup2(float w) {
    unsigned long long r;
    asm("mov.b64 %0, {%1, %1};" : "=l"(r) : "r"(__float_as_uint(w)));
    return r;
}
__device__ __forceinline__ void cp16(unsigned dst, const float* src) {
    asm volatile("cp.async.cg.shared.global [%0], [%1], 16;" :: "r"(dst), "l"(src));
}
__device__ __forceinline__ void cpcommit() {
    asm volatile("cp.async.commit_group;");
}
template<int N> __device__ __forceinline__ void cpwait() {
    asm volatile("cp.async.wait_group %0;" :: "n"(N));
}

// ---------------------------------------------------------------------------
// Prep 1: WeffT[k][h] = |W_rec[h][k]| * sign(k) * conn(h,k), diag 0.
// ---------------------------------------------------------------------------
__global__ void prep_weights(const float* __restrict__ Wrec) {
    __shared__ float tS[32][33];
    int h0 = blockIdx.x * 32, k0 = blockIdx.y * 32;
    int tid = threadIdx.x;                 // 128 threads
    for (int r = 0; r < 8; ++r) {
        int flat = tid + r * 128;
        int i = flat >> 5, kk = flat & 31;
        int h = h0 + i, k = k0 + kk;
        int ar = area_of(h);
        int conn; float sgn;
        if (k < ESZ) { int d = ar - (k >> 9); conn = (d >= -1 && d <= 1); sgn = 1.0f; }
        else         { conn = ((k - ESZ) >> 7) == ar;                     sgn = -1.0f; }
        float m = (conn && (h != k)) ? sgn : 0.0f;
        tS[kk][i] = fabsf(Wrec[h * H + k]) * m;
    }
    __syncthreads();
    for (int r = 0; r < 8; ++r) {
        int flat = tid + r * 128;
        int kk = flat >> 5, i = flat & 31;
        g_WeffT[(k0 + kk) * H + h0 + i] = tS[kk][i];
    }
}

// ---------------------------------------------------------------------------
// Prep 2: state [h][b] + initial activation [h][b]
// ---------------------------------------------------------------------------
__global__ void prep_state(const float* __restrict__ state0) {
    int idx = blockIdx.x * blockDim.x + threadIdx.x;
    if (idx >= NB * H) return;
    int b = idx / H, h = idx % H;
    float s = state0[idx];
    g_state[h * NB + b] = s;
    g_actT[h * NB + b] = tanhf(fmaxf(s, 0.0f));
}

// ---------------------------------------------------------------------------
// Prep 3: input drive for all timesteps (area-0 rows only)
// ---------------------------------------------------------------------------
__global__ void prep_input(const float* __restrict__ x, const float* __restrict__ Win) {
    int t   = blockIdx.y;
    int hp0 = blockIdx.x * 16;
    __shared__ float xS[64 * 133];
    __shared__ float wS[16 * 128];

    for (int r = threadIdx.x; r < 64 * 128; r += blockDim.x) {
        int bb = r >> 7, kk = r & 127;
        xS[bb * 133 + kk] = fmaxf(x[t * (NB * INSZ) + r], 0.0f);
    }
    for (int r = threadIdx.x; r < 16 * 128; r += blockDim.x) {
        int i = r >> 7, kk = r & 127;
        int hp = hp0 + i;
        int h  = (hp < EPER) ? hp : (ESZ + (hp - EPER));
        wS[r] = fabsf(Win[h * INSZ + kk]);
    }
    __syncthreads();

    int b  = threadIdx.x & 63;
    int hq = threadIdx.x >> 6;
    float acc[4] = {0.f, 0.f, 0.f, 0.f};
    for (int k = 0; k < 128; ++k) {
        float xv = xS[b * 133 + k];
#pragma unroll
        for (int j = 0; j < 4; ++j)
            acc[j] = fmaf(xv, wS[(hq * 4 + j) * 128 + k], acc[j]);
    }
#pragma unroll
    for (int j = 0; j < 4; ++j)
        g_Iin[(t * NIN_ROWS + hp0 + hq * 4 + j) * NB + b] = acc[j];
}

// ---------------------------------------------------------------------------
// Step kernel A: block-sparse partial GEMM, cp.async double-buffered.
//   CTA: 256 threads, tile 128h x 64b, thread tile 4h x 8b (FFMA2).
//   grid = 300 (load-balanced tile/slot schedule, one wave, ~3 chunks/CTA).
// ---------------------------------------------------------------------------
__global__ void __launch_bounds__(256) step_partial() {
    const int bid = blockIdx.x;
    int tile = 0;
#pragma unroll
    for (int t = 1; t < NTILE; ++t)
        if (bid >= cBase[t]) tile = t;
    const int slot = bid - cBase[tile];
    const int S    = cS[tile];
    const int area = cArea[tile];
    const int h0   = tile * 128;
    const int aE0 = (area > 0 ? area - 1 : 0);
    const int aE1 = (area < 3 ? area + 1 : 3);
    const int k0E = aE0 * EPER;
    const int lenE = (aE1 - aE0 + 1) * EPER;
    const int k0I = ESZ + area * IPER;
    const int nch = (lenE + IPER) >> 5;       // 36 or 52
    const int cb = (slot * nch) / S;
    const int ce = ((slot + 1) * nch) / S;

    __shared__ float actS[2][32 * 64];        // [buf][k][b]   8KB each
    __shared__ float wS[2][32 * 128];         // [buf][k][h']  16KB each

    const int tid = threadIdx.x;
    const int tx = tid & 7;                   // b-group (8 b)
    const int ty = tid >> 3;                  // h-group (4 h), 0..31

    unsigned actS_u = (unsigned)__cvta_generic_to_shared(&actS[0][0]);
    unsigned wS_u   = (unsigned)__cvta_generic_to_shared(&wS[0][0]);

    unsigned long long acc[4][4];
#pragma unroll
    for (int j = 0; j < 4; ++j)
#pragma unroll
        for (int p = 0; p < 4; ++p) acc[j][p] = 0ull;

    // async-copy one chunk (32 k) into buffer `buf`
    auto issue = [&](int c, int buf) {
        int off = c * 32;
        int kg = (off < lenE) ? (k0E + off) : (k0I + (off - lenE));
        // act: contiguous 2048 floats at g_actT + kg*64
        unsigned aB = actS_u + buf * 8192;
        const float* asrc = g_actT + kg * 64;
        cp16(aB + tid * 16,        asrc + tid * 4);
        cp16(aB + tid * 16 + 4096, asrc + 1024 + tid * 4);
        // w: 32 rows of 128 floats from g_WeffT[(kg+kk)*H + h0]
        unsigned wB = wS_u + buf * 16384;
#pragma unroll
        for (int r = 0; r < 4; ++r) {
            int u = tid + r * 256;            // 16B unit index, 0..1023
            int kk = u >> 5, col = u & 31;
            cp16(wB + u * 16, g_WeffT + (kg + kk) * H + h0 + col * 4);
        }
    };

    issue(cb, 0);
    cpcommit();

    for (int c = cb; c < ce; ++c) {
        int cur = (c - cb) & 1;
        bool more = (c + 1 < ce);
        if (more) { issue(c + 1, cur ^ 1); cpcommit(); }
        if (more) cpwait<1>(); else cpwait<0>();
        __syncthreads();

        unsigned aB = actS_u + cur * 8192;
        unsigned wB = wS_u + cur * 16384;
#pragma unroll
        for (int k = 0; k < 32; ++k) {
            unsigned long long a0, a1, a2, a3;
            unsigned aaddr = aB + k * 256 + tx * 32;
            asm volatile("ld.shared.v2.b64 {%0,%1}, [%2];"
                         : "=l"(a0), "=l"(a1) : "r"(aaddr));
            asm volatile("ld.shared.v2.b64 {%0,%1}, [%2+16];"
                         : "=l"(a2), "=l"(a3) : "r"(aaddr));
            float4 w4;
            unsigned waddr = wB + k * 512 + ty * 16;
            asm volatile("ld.shared.v4.f32 {%0,%1,%2,%3}, [%4];"
                         : "=f"(w4.x), "=f"(w4.y), "=f"(w4.z), "=f"(w4.w) : "r"(waddr));
            unsigned long long w0 = dup2(w4.x), w1 = dup2(w4.y),
                               w2 = dup2(w4.z), w3 = dup2(w4.w);
            ffma2(acc[0][0], a0, w0); ffma2(acc[0][1], a1, w0);
            ffma2(acc[0][2], a2, w0); ffma2(acc[0][3], a3, w0);
            ffma2(acc[1][0], a0, w1); ffma2(acc[1][1], a1, w1);
            ffma2(acc[1][2], a2, w1); ffma2(acc[1][3], a3, w1);
            ffma2(acc[2][0], a0, w2); ffma2(acc[2][1], a1, w2);
            ffma2(acc[2][2], a2, w2); ffma2(acc[2][3], a3, w2);
            ffma2(acc[3][0], a0, w3); ffma2(acc[3][1], a1, w3);
            ffma2(acc[3][2], a2, w3); ffma2(acc[3][3], a3, w3);
        }
        __syncthreads();
    }

    // write partials: g_P[bid][hl][b], 8 consecutive b per thread
#pragma unroll
    for (int j = 0; j < 4; ++j) {
        int hl = ty * 4 + j;
        UF2 u0, u1, u2, u3;
        u0.u = acc[j][0]; u1.u = acc[j][1]; u2.u = acc[j][2]; u3.u = acc[j][3];
        float* dst = g_P + (bid * 128 + hl) * NB + tx * 8;
        *reinterpret_cast<float4*>(dst)     = make_float4(u0.f.x, u0.f.y, u1.f.x, u1.f.y);
        *reinterpret_cast<float4*>(dst + 4) = make_float4(u2.f.x, u2.f.y, u3.f.x, u3.f.y);
    }
}

// ---------------------------------------------------------------------------
// Step kernel B: reduce slot partials + bias + input, leaky update, retanh.
// Writes g_state [h][b], g_actT [h][b], out[t][b][h].
// ---------------------------------------------------------------------------
__global__ void step_update(const float* __restrict__ b_rec, float* __restrict__ out, int t) {
    int h0 = blockIdx.x * 16;
    int tile = h0 >> 7;
    int base = cBase[tile], S = cS[tile];
    bool hasIn = (h0 < EPER) || (h0 >= ESZ && h0 < ESZ + IPER);
    int b  = threadIdx.x & 63;
    int hq = threadIdx.x >> 6;
    __shared__ float outS[16 * 65];

#pragma unroll
    for (int j = 0; j < 4; ++j) {
        int hl = hq * 4 + j;
        int h  = h0 + hl;
        int hloc = h & 127;
        float p = 0.f;
        for (int s = 0; s < S; ++s)
            p += g_P[((base + s) * 128 + hloc) * NB + b];
        p += b_rec[h];
        if (hasIn) {
            int hp = (h < EPER) ? h : (EPER + (h - ESZ));
            p += g_Iin[(t * NIN_ROWS + hp) * NB + b];
        }
        float s0 = g_state[h * NB + b];
        float ns = s0 * 0.8f + 0.2f * p;
        g_state[h * NB + b] = ns;
        float a = tanhf(fmaxf(ns, 0.0f));
        g_actT[h * NB + b] = a;
        outS[hl * 65 + b] = a;
    }
    __syncthreads();

    int b2 = threadIdx.x >> 2;
    int jq = threadIdx.x & 3;
    float4 v;
    v.x = outS[(jq * 4 + 0) * 65 + b2];
    v.y = outS[(jq * 4 + 1) * 65 + b2];
    v.z = outS[(jq * 4 + 2) * 65 + b2];
    v.w = outS[(jq * 4 + 3) * 65 + b2];
    *reinterpret_cast<float4*>(&out[(t * NB + b2) * H + h0 + jq * 4]) = v;
}

// ---------------------------------------------------------------------------
extern "C" void kernel_launch(void* const* d_in, const int* in_sizes, int n_in,
                              void* d_out, int out_size) {
    (void)in_sizes; (void)n_in; (void)out_size;
    const float* x      = (const float*)d_in[0];
    const float* W_in   = (const float*)d_in[1];
    const float* W_rec  = (const float*)d_in[2];
    const float* b_rec  = (const float*)d_in[3];
    const float* state0 = (const float*)d_in[4];
    float* out = (float*)d_out;

    prep_weights<<<dim3(H / 32, H / 32), 128>>>(W_rec);
    prep_state<<<(NB * H + 255) / 256, 256>>>(state0);
    prep_input<<<dim3(NIN_ROWS / 16, NT), 256>>>(x, W_in);

    for (int t = 0; t < NT; ++t) {
        step_partial<<<NSLOT, 256>>>();
        step_update<<<H / 16, 256>>>(b_rec, out, t);
    }
}

// round 5
// speedup vs baseline: 1.2742x; 1.2051x over previous
#include <cuda_runtime.h>
#include <math.h>

// Problem constants
#define H      2560
#define ESZ    2048
#define EPER   512
#define IPER   128
#define NB     64
#define NT     32
#define INSZ   128
#define NIN_ROWS 640
#define NTILE  20          // h-tiles of 128
#define NSLOT  300         // total (tile, slot) CTAs per step
#define SMEM_BYTES (3*8192 + 3*16384)   // 72 KB: 3x act(8KB) + 3x w(16KB)

// Static schedule: 36-chunk tiles get 12 slots, 52-chunk tiles get 18.
__constant__ int cS[NTILE]    = {12,12,12,12, 18,18,18,18, 18,18,18,18, 12,12,12,12, 12,18,18,12};
__constant__ int cBase[NTILE] = {0,12,24,36, 48,66,84,102, 120,138,156,174, 192,204,216,228, 240,252,270,288};
__constant__ int cArea[NTILE] = {0,0,0,0, 1,1,1,1, 2,2,2,2, 3,3,3,3, 0,1,2,3};

// Scratch (device globals: allocation-free rule)
__device__ float g_WeffT[H * H];                // |W_rec|*mask, TRANSPOSED: [k][h]
__device__ float g_P[NSLOT * 128 * NB];         // partials [globalSlot][h_local(128)][b]
__device__ float g_Iin[NT * NIN_ROWS * NB];     // precomputed input drive [t][h'][b]
__device__ float g_state[H * NB];               // state, [h][b]
__device__ float g_actT[H * NB];                // retanh(state_t), [h][b]

__device__ __forceinline__ int area_of(int u) {
    return u < ESZ ? (u >> 9) : ((u - ESZ) >> 7);
}

union UF2 { unsigned long long u; float2 f; };

__device__ __forceinline__ void ffma2(unsigned long long& d,
                                      unsigned long long a,
                                      unsigned long long b) {
    asm("fma.rn.f32x2 %0, %1, %2, %0;" : "+l"(d) : "l"(a), "l"(b));
}
__device__ __forceinline__ unsigned long long dup2(float w) {
    unsigned long long r;
    asm("mov.b64 %0, {%1, %1};" : "=l"(r) : "r"(__float_as_uint(w)));
    return r;
}
__device__ __forceinline__ void cp16(unsigned dst, const float* src) {
    asm volatile("cp.async.cg.shared.global [%0], [%1], 16;" :: "r"(dst), "l"(src));
}
__device__ __forceinline__ void cpcommit() {
    asm volatile("cp.async.commit_group;");
}
template<int N> __device__ __forceinline__ void cpwait() {
    asm volatile("cp.async.wait_group %0;" :: "n"(N));
}

// ---------------------------------------------------------------------------
// Prep 1: WeffT[k][h] = |W_rec[h][k]| * sign(k) * conn(h,k), diag 0.
// ---------------------------------------------------------------------------
__global__ void prep_weights(const float* __restrict__ Wrec) {
    __shared__ float tS[32][33];
    int h0 = blockIdx.x * 32, k0 = blockIdx.y * 32;
    int tid = threadIdx.x;                 // 128 threads
    for (int r = 0; r < 8; ++r) {
        int flat = tid + r * 128;
        int i = flat >> 5, kk = flat & 31;
        int h = h0 + i, k = k0 + kk;
        int ar = area_of(h);
        int conn; float sgn;
        if (k < ESZ) { int d = ar - (k >> 9); conn = (d >= -1 && d <= 1); sgn = 1.0f; }
        else         { conn = ((k - ESZ) >> 7) == ar;                     sgn = -1.0f; }
        float m = (conn && (h != k)) ? sgn : 0.0f;
        tS[kk][i] = fabsf(Wrec[h * H + k]) * m;
    }
    __syncthreads();
    for (int r = 0; r < 8; ++r) {
        int flat = tid + r * 128;
        int kk = flat >> 5, i = flat & 31;
        g_WeffT[(k0 + kk) * H + h0 + i] = tS[kk][i];
    }
}

// ---------------------------------------------------------------------------
// Prep 2: state [h][b] + initial activation [h][b]
// ---------------------------------------------------------------------------
__global__ void prep_state(const float* __restrict__ state0) {
    int idx = blockIdx.x * blockDim.x + threadIdx.x;
    if (idx >= NB * H) return;
    int b = idx / H, h = idx % H;
    float s = state0[idx];
    g_state[h * NB + b] = s;
    g_actT[h * NB + b] = tanhf(fmaxf(s, 0.0f));
}

// ---------------------------------------------------------------------------
// Prep 3: input drive for all timesteps (area-0 rows only)
// ---------------------------------------------------------------------------
__global__ void prep_input(const float* __restrict__ x, const float* __restrict__ Win) {
    int t   = blockIdx.y;
    int hp0 = blockIdx.x * 16;
    __shared__ float xS[64 * 133];
    __shared__ float wS[16 * 128];

    for (int r = threadIdx.x; r < 64 * 128; r += blockDim.x) {
        int bb = r >> 7, kk = r & 127;
        xS[bb * 133 + kk] = fmaxf(x[t * (NB * INSZ) + r], 0.0f);
    }
    for (int r = threadIdx.x; r < 16 * 128; r += blockDim.x) {
        int i = r >> 7, kk = r & 127;
        int hp = hp0 + i;
        int h  = (hp < EPER) ? hp : (ESZ + (hp - EPER));
        wS[r] = fabsf(Win[h * INSZ + kk]);
    }
    __syncthreads();

    int b  = threadIdx.x & 63;
    int hq = threadIdx.x >> 6;
    float acc[4] = {0.f, 0.f, 0.f, 0.f};
    for (int k = 0; k < 128; ++k) {
        float xv = xS[b * 133 + k];
#pragma unroll
        for (int j = 0; j < 4; ++j)
            acc[j] = fmaf(xv, wS[(hq * 4 + j) * 128 + k], acc[j]);
    }
#pragma unroll
    for (int j = 0; j < 4; ++j)
        g_Iin[(t * NIN_ROWS + hp0 + hq * 4 + j) * NB + b] = acc[j];
}

// ---------------------------------------------------------------------------
// Step kernel A: block-sparse partial GEMM.
//   CTA: 128 threads, tile 128h x 64b, thread tile 8h x 8b (32 FFMA2 per k).
//   Triple-buffered cp.async (1 barrier/chunk). grid = 300 balanced slots.
// ---------------------------------------------------------------------------
__global__ void __launch_bounds__(128) step_partial() {
    extern __shared__ float sm[];
    const int bid = blockIdx.x;
    int tile = 0;
#pragma unroll
    for (int t = 1; t < NTILE; ++t)
        if (bid >= cBase[t]) tile = t;
    const int slot = bid - cBase[tile];
    const int S    = cS[tile];
    const int area = cArea[tile];
    const int h0   = tile * 128;
    const int aE0 = (area > 0 ? area - 1 : 0);
    const int aE1 = (area < 3 ? area + 1 : 3);
    const int k0E = aE0 * EPER;
    const int lenE = (aE1 - aE0 + 1) * EPER;
    const int k0I = ESZ + area * IPER;
    const int nch = (lenE + IPER) >> 5;       // 36 or 52
    const int cb = (slot * nch) / S;
    const int ce = ((slot + 1) * nch) / S;

    const int tid = threadIdx.x;
    const int tx = tid & 7;                   // b-group (8 b)
    const int ty = tid >> 3;                  // h-group (8 h), 0..15

    unsigned actS_u = (unsigned)__cvta_generic_to_shared(sm);              // 3 x 8KB
    unsigned wS_u   = (unsigned)__cvta_generic_to_shared(sm + 3 * 2048);   // 3 x 16KB

    unsigned long long acc[8][4];
#pragma unroll
    for (int j = 0; j < 8; ++j)
#pragma unroll
        for (int p = 0; p < 4; ++p) acc[j][p] = 0ull;

    // async-copy one chunk (32 k) into buffer `buf`
    auto issue = [&](int c, int buf) {
        int off = c * 32;
        int kg = (off < lenE) ? (k0E + off) : (k0I + (off - lenE));
        unsigned aB = actS_u + buf * 8192;
        const float* asrc = g_actT + kg * 64;     // 2048 contiguous floats
#pragma unroll
        for (int r = 0; r < 4; ++r) {
            int u = tid + r * 128;
            cp16(aB + u * 16, asrc + u * 4);
        }
        unsigned wB = wS_u + buf * 16384;         // 32 rows x 128 floats
#pragma unroll
        for (int r = 0; r < 8; ++r) {
            int u = tid + r * 128;                // 16B unit, 0..1023
            int kk = u >> 5, col = u & 31;
            cp16(wB + u * 16, g_WeffT + (kg + kk) * H + h0 + col * 4);
        }
    };

    for (int c = cb; c < ce; ++c) {
        if (c == cb) { issue(c, 0); cpcommit(); }
        if (c + 1 < ce) { issue(c + 1, (c + 1 - cb) % 3); cpcommit(); cpwait<1>(); }
        else cpwait<0>();
        __syncthreads();

        int buf = (c - cb) % 3;
        unsigned aB = actS_u + buf * 8192;
        unsigned wB = wS_u + buf * 16384;
#pragma unroll
        for (int k = 0; k < 32; ++k) {
            unsigned long long a0, a1, a2, a3;
            unsigned aaddr = aB + k * 256 + tx * 32;
            asm volatile("ld.shared.v2.b64 {%0,%1}, [%2];"
                         : "=l"(a0), "=l"(a1) : "r"(aaddr));
            asm volatile("ld.shared.v2.b64 {%0,%1}, [%2+16];"
                         : "=l"(a2), "=l"(a3) : "r"(aaddr));
            float w0, w1, w2, w3, w4, w5, w6, w7;
            unsigned waddr = wB + k * 512 + ty * 32;
            asm volatile("ld.shared.v4.f32 {%0,%1,%2,%3}, [%4];"
                         : "=f"(w0), "=f"(w1), "=f"(w2), "=f"(w3) : "r"(waddr));
            asm volatile("ld.shared.v4.f32 {%0,%1,%2,%3}, [%4+16];"
                         : "=f"(w4), "=f"(w5), "=f"(w6), "=f"(w7) : "r"(waddr));
            unsigned long long d0 = dup2(w0), d1 = dup2(w1), d2 = dup2(w2), d3 = dup2(w3);
            unsigned long long d4 = dup2(w4), d5 = dup2(w5), d6 = dup2(w6), d7 = dup2(w7);
            ffma2(acc[0][0], a0, d0); ffma2(acc[0][1], a1, d0);
            ffma2(acc[0][2], a2, d0); ffma2(acc[0][3], a3, d0);
            ffma2(acc[1][0], a0, d1); ffma2(acc[1][1], a1, d1);
            ffma2(acc[1][2], a2, d1); ffma2(acc[1][3], a3, d1);
            ffma2(acc[2][0], a0, d2); ffma2(acc[2][1], a1, d2);
            ffma2(acc[2][2], a2, d2); ffma2(acc[2][3], a3, d2);
            ffma2(acc[3][0], a0, d3); ffma2(acc[3][1], a1, d3);
            ffma2(acc[3][2], a2, d3); ffma2(acc[3][3], a3, d3);
            ffma2(acc[4][0], a0, d4); ffma2(acc[4][1], a1, d4);
            ffma2(acc[4][2], a2, d4); ffma2(acc[4][3], a3, d4);
            ffma2(acc[5][0], a0, d5); ffma2(acc[5][1], a1, d5);
            ffma2(acc[5][2], a2, d5); ffma2(acc[5][3], a3, d5);
            ffma2(acc[6][0], a0, d6); ffma2(acc[6][1], a1, d6);
            ffma2(acc[6][2], a2, d6); ffma2(acc[6][3], a3, d6);
            ffma2(acc[7][0], a0, d7); ffma2(acc[7][1], a1, d7);
            ffma2(acc[7][2], a2, d7); ffma2(acc[7][3], a3, d7);
        }
        __syncthreads();
    }

    // write partials: g_P[bid][hl][b], 8 consecutive b per thread, 8 h rows
#pragma unroll
    for (int j = 0; j < 8; ++j) {
        int hl = ty * 8 + j;
        UF2 u0, u1, u2, u3;
        u0.u = acc[j][0]; u1.u = acc[j][1]; u2.u = acc[j][2]; u3.u = acc[j][3];
        float* dst = g_P + (bid * 128 + hl) * NB + tx * 8;
        *reinterpret_cast<float4*>(dst)     = make_float4(u0.f.x, u0.f.y, u1.f.x, u1.f.y);
        *reinterpret_cast<float4*>(dst + 4) = make_float4(u2.f.x, u2.f.y, u3.f.x, u3.f.y);
    }
}

// ---------------------------------------------------------------------------
// Step kernel B: reduce slot partials + bias + input, leaky update, retanh.
// ---------------------------------------------------------------------------
__global__ void step_update(const float* __restrict__ b_rec, float* __restrict__ out, int t) {
    int h0 = blockIdx.x * 16;
    int tile = h0 >> 7;
    int base = cBase[tile], S = cS[tile];
    bool hasIn = (h0 < EPER) || (h0 >= ESZ && h0 < ESZ + IPER);
    int b  = threadIdx.x & 63;
    int hq = threadIdx.x >> 6;
    __shared__ float outS[16 * 65];

#pragma unroll
    for (int j = 0; j < 4; ++j) {
        int hl = hq * 4 + j;
        int h  = h0 + hl;
        int hloc = h & 127;
        float p = 0.f;
        for (int s = 0; s < S; ++s)
            p += g_P[((base + s) * 128 + hloc) * NB + b];
        p += b_rec[h];
        if (hasIn) {
            int hp = (h < EPER) ? h : (EPER + (h - ESZ));
            p += g_Iin[(t * NIN_ROWS + hp) * NB + b];
        }
        float s0 = g_state[h * NB + b];
        float ns = s0 * 0.8f + 0.2f * p;
        g_state[h * NB + b] = ns;
        float a = tanhf(fmaxf(ns, 0.0f));
        g_actT[h * NB + b] = a;
        outS[hl * 65 + b] = a;
    }
    __syncthreads();

    int b2 = threadIdx.x >> 2;
    int jq = threadIdx.x & 3;
    float4 v;
    v.x = outS[(jq * 4 + 0) * 65 + b2];
    v.y = outS[(jq * 4 + 1) * 65 + b2];
    v.z = outS[(jq * 4 + 2) * 65 + b2];
    v.w = outS[(jq * 4 + 3) * 65 + b2];
    *reinterpret_cast<float4*>(&out[(t * NB + b2) * H + h0 + jq * 4]) = v;
}

// ---------------------------------------------------------------------------
extern "C" void kernel_launch(void* const* d_in, const int* in_sizes, int n_in,
                              void* d_out, int out_size) {
    (void)in_sizes; (void)n_in; (void)out_size;
    const float* x      = (const float*)d_in[0];
    const float* W_in   = (const float*)d_in[1];
    const float* W_rec  = (const float*)d_in[2];
    const float* b_rec  = (const float*)d_in[3];
    const float* state0 = (const float*)d_in[4];
    float* out = (float*)d_out;

    cudaFuncSetAttribute(step_partial,
                         cudaFuncAttributeMaxDynamicSharedMemorySize, SMEM_BYTES);

    prep_weights<<<dim3(H / 32, H / 32), 128>>>(W_rec);
    prep_state<<<(NB * H + 255) / 256, 256>>>(state0);
    prep_input<<<dim3(NIN_ROWS / 16, NT), 256>>>(x, W_in);

    for (int t = 0; t < NT; ++t) {
        step_partial<<<NSLOT, 128, SMEM_BYTES>>>();
        step_update<<<H / 16, 256>>>(b_rec, out, t);
    }
}

// round 7
// speedup vs baseline: 1.5006x; 1.1776x over previous
#include <cuda_runtime.h>
#include <math.h>

// Problem constants
#define H      2560
#define ESZ    2048
#define EPER   512
#define IPER   128
#define NB     64
#define NT     32
#define INSZ   128
#define NIN_ROWS 640
#define NTILE  20
#define NCTA   290
// smem: 4 weight chunks (4*4096 floats) + 3 act buffers (3*2048 floats) = 88 KB
#define SMEM_FLOATS (4*4096 + 3*2048)
#define SMEM_BYTES  (SMEM_FLOATS * 4)

// Correct schedule. Tiles of 128 h-rows: tiles 0-15 are E (area = tile/4),
// tiles 16-19 are I (area = tile-16). Areas 0,3 -> 36 K-chunks -> 12 slots;
// areas 1,2 -> 52 K-chunks -> 17 slots. Total = 10*12 + 10*17 = 290 CTAs.
__constant__ int cArea[NTILE] = {0,0,0,0, 1,1,1,1, 2,2,2,2, 3,3,3,3, 0,1,2,3};
__constant__ int cS[NTILE]    = {12,12,12,12, 17,17,17,17, 17,17,17,17, 12,12,12,12, 12,17,17,12};
__constant__ int cBase[NTILE] = {0,12,24,36, 48,65,82,99, 116,133,150,167, 184,196,208,220, 232,244,261,278};

// Scratch (device globals: allocation-free rule)
__device__ float g_WeffT[H * H];               // |W_rec|*mask, transposed [k][h]
__device__ float g_P[NCTA * 128 * NB];         // partials [globalSlot][h_local][b]
__device__ float g_Iin[NT * NIN_ROWS * NB];    // input drive [t][h'][b]
__device__ float g_state[H * NB];              // state [h][b]
__device__ float g_actT[H * NB];               // retanh(state) [h][b]

// Global barrier state (8 padded first-level counters + level-2 + epoch)
__device__ unsigned g_cnt[8 * 32];
__device__ unsigned g_cnt2;
__device__ unsigned g_epoch;

__device__ __forceinline__ int area_of(int u) {
    return u < ESZ ? (u >> 9) : ((u - ESZ) >> 7);
}

union UF2 { unsigned long long u; float2 f; };

__device__ __forceinline__ void ffma2(unsigned long long& d,
                                      unsigned long long a,
                                      unsigned long long b) {
    asm("fma.rn.f32x2 %0, %1, %2, %0;" : "+l"(d) : "l"(a), "l"(b));
}
__device__ __forceinline__ unsigned long long dup2(float w) {
    unsigned long long r;
    asm("mov.b64 %0, {%1, %1};" : "=l"(r) : "r"(__float_as_uint(w)));
    return r;
}
__device__ __forceinline__ void cp16(unsigned dst, const float* src) {
    asm volatile("cp.async.cg.shared.global [%0], [%1], 16;" :: "r"(dst), "l"(src));
}
__device__ __forceinline__ void cpcommit() {
    asm volatile("cp.async.commit_group;");
}
template<int N> __device__ __forceinline__ void cpwait() {
    asm volatile("cp.async.wait_group %0;" :: "n"(N));
}

__device__ __forceinline__ unsigned grpCount(int i) {
    return (unsigned)((NCTA - i + 7) / 8);
}

// device-wide epoch barrier (all NCTA CTAs resident)
__device__ __forceinline__ void gbar(int bid, unsigned target) {
    __syncthreads();
    if (threadIdx.x == 0) {
        __threadfence();
        int g = bid & 7;
        if (atomicAdd(&g_cnt[g * 32], 1) == grpCount(g) - 1) {
            atomicExch(&g_cnt[g * 32], 0);
            if (atomicAdd(&g_cnt2, 1) == 7) {
                atomicExch(&g_cnt2, 0);
                __threadfence();
                atomicAdd(&g_epoch, 1);
            }
        }
        while (*(volatile unsigned*)&g_epoch < target) __nanosleep(32);
        __threadfence();
    }
    __syncthreads();
}

// ---------------------------------------------------------------------------
__global__ void init_bar() {
    if (threadIdx.x < 8) g_cnt[threadIdx.x * 32] = 0;
    if (threadIdx.x == 8) g_cnt2 = 0;
    if (threadIdx.x == 9) g_epoch = 0;
}

// ---------------------------------------------------------------------------
// Prep 1: WeffT[k][h] = |W_rec[h][k]| * sign(k) * conn(h,k), diag 0.
// ---------------------------------------------------------------------------
__global__ void prep_weights(const float* __restrict__ Wrec) {
    __shared__ float tS[32][33];
    int h0 = blockIdx.x * 32, k0 = blockIdx.y * 32;
    int tid = threadIdx.x;
    for (int r = 0; r < 8; ++r) {
        int flat = tid + r * 128;
        int i = flat >> 5, kk = flat & 31;
        int h = h0 + i, k = k0 + kk;
        int ar = area_of(h);
        int conn; float sgn;
        if (k < ESZ) { int d = ar - (k >> 9); conn = (d >= -1 && d <= 1); sgn = 1.0f; }
        else         { conn = ((k - ESZ) >> 7) == ar;                     sgn = -1.0f; }
        float m = (conn && (h != k)) ? sgn : 0.0f;
        tS[kk][i] = fabsf(Wrec[h * H + k]) * m;
    }
    __syncthreads();
    for (int r = 0; r < 8; ++r) {
        int flat = tid + r * 128;
        int kk = flat >> 5, i = flat & 31;
        g_WeffT[(k0 + kk) * H + h0 + i] = tS[kk][i];
    }
}

// ---------------------------------------------------------------------------
__global__ void prep_state(const float* __restrict__ state0) {
    int idx = blockIdx.x * blockDim.x + threadIdx.x;
    if (idx >= NB * H) return;
    int b = idx / H, h = idx % H;
    float s = state0[idx];
    g_state[h * NB + b] = s;
    g_actT[h * NB + b] = tanhf(fmaxf(s, 0.0f));
}

// ---------------------------------------------------------------------------
__global__ void prep_input(const float* __restrict__ x, const float* __restrict__ Win) {
    int t   = blockIdx.y;
    int hp0 = blockIdx.x * 16;
    __shared__ float xS[64 * 133];
    __shared__ float wS[16 * 128];

    for (int r = threadIdx.x; r < 64 * 128; r += blockDim.x) {
        int bb = r >> 7, kk = r & 127;
        xS[bb * 133 + kk] = fmaxf(x[t * (NB * INSZ) + r], 0.0f);
    }
    for (int r = threadIdx.x; r < 16 * 128; r += blockDim.x) {
        int i = r >> 7, kk = r & 127;
        int hp = hp0 + i;
        int h  = (hp < EPER) ? hp : (ESZ + (hp - EPER));
        wS[r] = fabsf(Win[h * INSZ + kk]);
    }
    __syncthreads();

    int b  = threadIdx.x & 63;
    int hq = threadIdx.x >> 6;
    float acc[4] = {0.f, 0.f, 0.f, 0.f};
    for (int k = 0; k < 128; ++k) {
        float xv = xS[b * 133 + k];
#pragma unroll
        for (int j = 0; j < 4; ++j)
            acc[j] = fmaf(xv, wS[(hq * 4 + j) * 128 + k], acc[j]);
    }
#pragma unroll
    for (int j = 0; j < 4; ++j)
        g_Iin[(t * NIN_ROWS + hp0 + hq * 4 + j) * NB + b] = acc[j];
}

// ---------------------------------------------------------------------------
// Persistent kernel: all 32 steps, weights resident in SMEM.
// ---------------------------------------------------------------------------
__global__ void __launch_bounds__(128) persist(const float* __restrict__ b_rec,
                                               float* __restrict__ out) {
    extern __shared__ float sm[];
    const int bid = blockIdx.x;

    int tile = 0;
#pragma unroll
    for (int t = 1; t < NTILE; ++t)
        if (bid >= cBase[t]) tile = t;
    const int slot  = bid - cBase[tile];
    const int S     = cS[tile];
    const int tbase = cBase[tile];
    const int area  = cArea[tile];
    const int h0    = tile * 128;

    const int aE0 = (area > 0 ? area - 1 : 0);
    const int aE1 = (area < 3 ? area + 1 : 3);
    const int k0E = aE0 * EPER;
    const int lenE = (aE1 - aE0 + 1) * EPER;
    const int k0I = ESZ + area * IPER;
    const int nch = (lenE + IPER) >> 5;            // 36 or 52
    const int cb = (slot * nch) / S;
    const int ce = ((slot + 1) * nch) / S;         // 3 or 4 chunks

    const int tid = threadIdx.x;
    const int tx = tid & 7;                        // b-group (8 b)
    const int ty = tid >> 3;                       // h-group (8 h), 0..15

    unsigned wS_u   = (unsigned)__cvta_generic_to_shared(sm);              // 4 x 16KB
    unsigned actS_u = (unsigned)__cvta_generic_to_shared(sm + 4 * 4096);   // 3 x 8KB

    auto kgOf = [&](int c) {
        int off = c * 32;
        return (off < lenE) ? (k0E + off) : (k0I + (off - lenE));
    };

    // ---- load this CTA's weight chunks ONCE ----
    for (int ci = 0; ci < ce - cb; ++ci) {
        int kg = kgOf(cb + ci);
        unsigned wB = wS_u + ci * 16384;
#pragma unroll
        for (int r = 0; r < 8; ++r) {
            int u = tid + r * 128;
            int kk = u >> 5, col = u & 31;
            cp16(wB + u * 16, g_WeffT + (kg + kk) * H + h0 + col * 4);
        }
    }
    cpcommit(); cpwait<0>(); __syncthreads();

    // update-phase row range for this slot
    const int rlo = (slot * 128) / S, rhi = ((slot + 1) * 128) / S;  // <= 11 rows
    const int rr = tid >> 4;                       // 0..7
    const int bq = tid & 15;                       // b-quad

    auto issueA = [&](int c, int buf) {
        int kg = kgOf(c);
        unsigned aB = actS_u + buf * 8192;
        const float* asrc = g_actT + kg * 64;
#pragma unroll
        for (int r = 0; r < 4; ++r) {
            int u = tid + r * 128;
            cp16(aB + u * 16, asrc + u * 4);
        }
    };

    unsigned ep = 0;
    for (int t = 0; t < NT; ++t) {
        unsigned long long acc[8][4];
#pragma unroll
        for (int j = 0; j < 8; ++j)
#pragma unroll
            for (int p = 0; p < 4; ++p) acc[j][p] = 0ull;

        issueA(cb, 0); cpcommit();
        for (int c = cb; c < ce; ++c) {
            if (c + 1 < ce) { issueA(c + 1, (c + 1 - cb) % 3); cpcommit(); cpwait<1>(); }
            else cpwait<0>();
            __syncthreads();

            unsigned aB = actS_u + ((c - cb) % 3) * 8192;
            unsigned wB = wS_u + (c - cb) * 16384;
#pragma unroll
            for (int k = 0; k < 32; ++k) {
                unsigned long long a0, a1, a2, a3;
                unsigned aaddr = aB + k * 256 + tx * 32;
                asm volatile("ld.shared.v2.b64 {%0,%1}, [%2];"
                             : "=l"(a0), "=l"(a1) : "r"(aaddr));
                asm volatile("ld.shared.v2.b64 {%0,%1}, [%2+16];"
                             : "=l"(a2), "=l"(a3) : "r"(aaddr));
                float w0, w1, w2, w3, w4, w5, w6, w7;
                unsigned waddr = wB + k * 512 + ty * 32;
                asm volatile("ld.shared.v4.f32 {%0,%1,%2,%3}, [%4];"
                             : "=f"(w0), "=f"(w1), "=f"(w2), "=f"(w3) : "r"(waddr));
                asm volatile("ld.shared.v4.f32 {%0,%1,%2,%3}, [%4+16];"
                             : "=f"(w4), "=f"(w5), "=f"(w6), "=f"(w7) : "r"(waddr));
                unsigned long long d0 = dup2(w0), d1 = dup2(w1), d2 = dup2(w2), d3 = dup2(w3);
                unsigned long long d4 = dup2(w4), d5 = dup2(w5), d6 = dup2(w6), d7 = dup2(w7);
                ffma2(acc[0][0], a0, d0); ffma2(acc[0][1], a1, d0);
                ffma2(acc[0][2], a2, d0); ffma2(acc[0][3], a3, d0);
                ffma2(acc[1][0], a0, d1); ffma2(acc[1][1], a1, d1);
                ffma2(acc[1][2], a2, d1); ffma2(acc[1][3], a3, d1);
                ffma2(acc[2][0], a0, d2); ffma2(acc[2][1], a1, d2);
                ffma2(acc[2][2], a2, d2); ffma2(acc[2][3], a3, d2);
                ffma2(acc[3][0], a0, d3); ffma2(acc[3][1], a1, d3);
                ffma2(acc[3][2], a2, d3); ffma2(acc[3][3], a3, d3);
                ffma2(acc[4][0], a0, d4); ffma2(acc[4][1], a1, d4);
                ffma2(acc[4][2], a2, d4); ffma2(acc[4][3], a3, d4);
                ffma2(acc[5][0], a0, d5); ffma2(acc[5][1], a1, d5);
                ffma2(acc[5][2], a2, d5); ffma2(acc[5][3], a3, d5);
                ffma2(acc[6][0], a0, d6); ffma2(acc[6][1], a1, d6);
                ffma2(acc[6][2], a2, d6); ffma2(acc[6][3], a3, d6);
                ffma2(acc[7][0], a0, d7); ffma2(acc[7][1], a1, d7);
                ffma2(acc[7][2], a2, d7); ffma2(acc[7][3], a3, d7);
            }
            __syncthreads();
        }

        // write partials
#pragma unroll
        for (int j = 0; j < 8; ++j) {
            int hl = ty * 8 + j;
            UF2 u0, u1, u2, u3;
            u0.u = acc[j][0]; u1.u = acc[j][1]; u2.u = acc[j][2]; u3.u = acc[j][3];
            float* dst = g_P + (bid * 128 + hl) * NB + tx * 8;
            *reinterpret_cast<float4*>(dst)     = make_float4(u0.f.x, u0.f.y, u1.f.x, u1.f.y);
            *reinterpret_cast<float4*>(dst + 4) = make_float4(u2.f.x, u2.f.y, u3.f.x, u3.f.y);
        }

        gbar(bid, ++ep);

        // ---- fused update phase: rows [rlo, rhi) of this tile ----
        for (int r = rlo + rr; r < rhi; r += 8) {
            int h = h0 + r;
            float4 p = make_float4(0.f, 0.f, 0.f, 0.f);
            for (int s = 0; s < S; ++s) {
                float4 v = *reinterpret_cast<const float4*>(
                    &g_P[((tbase + s) * 128 + r) * NB + bq * 4]);
                p.x += v.x; p.y += v.y; p.z += v.z; p.w += v.w;
            }
            float br = b_rec[h];
            p.x += br; p.y += br; p.z += br; p.w += br;
            if (h < EPER || (h >= ESZ && h < ESZ + IPER)) {
                int hp = (h < EPER) ? h : (EPER + (h - ESZ));
                float4 iv = *reinterpret_cast<const float4*>(
                    &g_Iin[(t * NIN_ROWS + hp) * NB + bq * 4]);
                p.x += iv.x; p.y += iv.y; p.z += iv.z; p.w += iv.w;
            }
            float4 st = *reinterpret_cast<const float4*>(&g_state[h * NB + bq * 4]);
            float4 ns;
            ns.x = st.x * 0.8f + 0.2f * p.x;
            ns.y = st.y * 0.8f + 0.2f * p.y;
            ns.z = st.z * 0.8f + 0.2f * p.z;
            ns.w = st.w * 0.8f + 0.2f * p.w;
            *reinterpret_cast<float4*>(&g_state[h * NB + bq * 4]) = ns;
            float4 a;
            a.x = tanhf(fmaxf(ns.x, 0.0f));
            a.y = tanhf(fmaxf(ns.y, 0.0f));
            a.z = tanhf(fmaxf(ns.z, 0.0f));
            a.w = tanhf(fmaxf(ns.w, 0.0f));
            *reinterpret_cast<float4*>(&g_actT[h * NB + bq * 4]) = a;
            out[(t * NB + bq * 4 + 0) * H + h] = a.x;
            out[(t * NB + bq * 4 + 1) * H + h] = a.y;
            out[(t * NB + bq * 4 + 2) * H + h] = a.z;
            out[(t * NB + bq * 4 + 3) * H + h] = a.w;
        }

        gbar(bid, ++ep);
    }
}

// ---------------------------------------------------------------------------
extern "C" void kernel_launch(void* const* d_in, const int* in_sizes, int n_in,
                              void* d_out, int out_size) {
    (void)in_sizes; (void)n_in; (void)out_size;
    const float* x      = (const float*)d_in[0];
    const float* W_in   = (const float*)d_in[1];
    const float* W_rec  = (const float*)d_in[2];
    const float* b_rec  = (const float*)d_in[3];
    const float* state0 = (const float*)d_in[4];
    float* out = (float*)d_out;

    cudaFuncSetAttribute(persist,
                         cudaFuncAttributeMaxDynamicSharedMemorySize, SMEM_BYTES);

    init_bar<<<1, 32>>>();
    prep_weights<<<dim3(H / 32, H / 32), 128>>>(W_rec);
    prep_state<<<(NB * H + 255) / 256, 256>>>(state0);
    prep_input<<<dim3(NIN_ROWS / 16, NT), 256>>>(x, W_in);

    persist<<<NCTA, 128, SMEM_BYTES>>>(b_rec, out);
}

// round 9
// speedup vs baseline: 1.5692x; 1.0457x over previous
#include <cuda_runtime.h>
#include <math.h>

// Problem constants
#define H      2560
#define ESZ    2048
#define EPER   512
#define IPER   128
#define NB     64
#define NT     32
#define INSZ   128
#define NIN_ROWS 640
#define NTILE  20
#define NCTA   440
// persist smem: 2 weight chunks (2*4096 floats) + 2 act buffers (2*2048) = 48 KB
#define SMEM_FLOATS (2*4096 + 2*2048)
#define SMEM_BYTES  (SMEM_FLOATS * 4)
// prep_input smem: 2 arrays of 128*68 floats (pad 68: float4-aligned)
#define PIN_PAD  68
#define PIN_SMEM (2 * 128 * PIN_PAD * 4)

// Schedule: tiles of 128 h-rows. Tiles 0-15 E (area=tile/4), 16-19 I (area=tile-16).
// Areas 0,3 -> 36 K-chunks -> 18 slots (2 each); areas 1,2 -> 52 -> 26 slots (2 each).
__constant__ int cArea[NTILE] = {0,0,0,0, 1,1,1,1, 2,2,2,2, 3,3,3,3, 0,1,2,3};
__constant__ int cS[NTILE]    = {18,18,18,18, 26,26,26,26, 26,26,26,26, 18,18,18,18, 18,26,26,18};
__constant__ int cBase[NTILE] = {0,18,36,54, 72,98,124,150, 176,202,228,254, 280,298,316,334, 352,370,396,422};

// Scratch (device globals)
__device__ float g_WeffT[H * H];               // |W_rec|*mask, transposed [k][h]
__device__ float g_P[NCTA * 128 * NB];         // partials [globalSlot][h_local][b]
__device__ float g_Iin[NT * NIN_ROWS * NB];    // input drive [t][h'][b]
__device__ float g_state[H * NB];              // state [h][b]
__device__ float g_actT[H * NB];               // retanh(state) [h][b]

// Global barrier state
__device__ unsigned g_cnt[8 * 32];
__device__ unsigned g_cnt2;
__device__ unsigned g_epoch;

__device__ __forceinline__ int area_of(int u) {
    return u < ESZ ? (u >> 9) : ((u - ESZ) >> 7);
}

union UF2 { unsigned long long u; float2 f; };

__device__ __forceinline__ void ffma2(unsigned long long& d,
                                      unsigned long long a,
                                      unsigned long long b) {
    asm("fma.rn.f32x2 %0, %1, %2, %0;" : "+l"(d) : "l"(a), "l"(b));
}
__device__ __forceinline__ unsigned long long dup2(float w) {
    unsigned long long r;
    asm("mov.b64 %0, {%1, %1};" : "=l"(r) : "r"(__float_as_uint(w)));
    return r;
}
__device__ __forceinline__ void cp16(unsigned dst, const float* src) {
    asm volatile("cp.async.cg.shared.global [%0], [%1], 16;" :: "r"(dst), "l"(src));
}
__device__ __forceinline__ void cpcommit() {
    asm volatile("cp.async.commit_group;");
}
template<int N> __device__ __forceinline__ void cpwait() {
    asm volatile("cp.async.wait_group %0;" :: "n"(N));
}

__device__ __forceinline__ unsigned grpCount(int i) {
    return (unsigned)((NCTA - i + 7) / 8);
}

// device-wide epoch barrier (all NCTA CTAs resident)
__device__ __forceinline__ void gbar(int bid, unsigned target) {
    __syncthreads();
    if (threadIdx.x == 0) {
        __threadfence();
        int g = bid & 7;
        if (atomicAdd(&g_cnt[g * 32], 1) == grpCount(g) - 1) {
            atomicExch(&g_cnt[g * 32], 0);
            if (atomicAdd(&g_cnt2, 1) == 7) {
                atomicExch(&g_cnt2, 0);
                __threadfence();
                atomicAdd(&g_epoch, 1);
            }
        }
        while (*(volatile unsigned*)&g_epoch < target) __nanosleep(32);
        __threadfence();
    }
    __syncthreads();
}

// ---------------------------------------------------------------------------
__global__ void init_bar() {
    if (threadIdx.x < 8) g_cnt[threadIdx.x * 32] = 0;
    if (threadIdx.x == 8) g_cnt2 = 0;
    if (threadIdx.x == 9) g_epoch = 0;
}

// ---------------------------------------------------------------------------
// Prep 1: WeffT[k][h] = |W_rec[h][k]| * sign(k) * conn(h,k), diag 0.
// ---------------------------------------------------------------------------
__global__ void prep_weights(const float* __restrict__ Wrec) {
    __shared__ float tS[32][33];
    int h0 = blockIdx.x * 32, k0 = blockIdx.y * 32;
    int tid = threadIdx.x;
    for (int r = 0; r < 8; ++r) {
        int flat = tid + r * 128;
        int i = flat >> 5, kk = flat & 31;
        int h = h0 + i, k = k0 + kk;
        int ar = area_of(h);
        int conn; float sgn;
        if (k < ESZ) { int d = ar - (k >> 9); conn = (d >= -1 && d <= 1); sgn = 1.0f; }
        else         { conn = ((k - ESZ) >> 7) == ar;                     sgn = -1.0f; }
        float m = (conn && (h != k)) ? sgn : 0.0f;
        tS[kk][i] = fabsf(Wrec[h * H + k]) * m;
    }
    __syncthreads();
    for (int r = 0; r < 8; ++r) {
        int flat = tid + r * 128;
        int kk = flat >> 5, i = flat & 31;
        g_WeffT[(k0 + kk) * H + h0 + i] = tS[kk][i];
    }
}

// ---------------------------------------------------------------------------
__global__ void prep_state(const float* __restrict__ state0) {
    int idx = blockIdx.x * blockDim.x + threadIdx.x;
    if (idx >= NB * H) return;
    int b = idx / H, h = idx % H;
    float s = state0[idx];
    g_state[h * NB + b] = s;
    g_actT[h * NB + b] = tanhf(fmaxf(s, 0.0f));
}

// ---------------------------------------------------------------------------
// Prep 3: input drive. grid (10 hp-tiles of 64, 32 t), 256 threads.
// Pad 68 (multiple of 4): float4-aligned reads, <=4-way conflicts on stores.
// ---------------------------------------------------------------------------
__global__ void prep_input(const float* __restrict__ x, const float* __restrict__ Win) {
    extern __shared__ float ps[];
    float* xS = ps;                       // [k][b], 128 x PIN_PAD
    float* wS = ps + 128 * PIN_PAD;       // [k][hp], 128 x PIN_PAD
    int t   = blockIdx.y;
    int hp0 = blockIdx.x * 64;

    for (int r = threadIdx.x; r < 64 * 128; r += 256) {
        int b = r >> 7, k = r & 127;
        xS[k * PIN_PAD + b] = fmaxf(x[t * (NB * INSZ) + r], 0.0f);
    }
    for (int r = threadIdx.x; r < 64 * 128; r += 256) {
        int i = r >> 7, k = r & 127;
        int hp = hp0 + i;
        int h  = (hp < EPER) ? hp : (ESZ + (hp - EPER));
        wS[k * PIN_PAD + i] = fabsf(Win[h * INSZ + k]);
    }
    __syncthreads();

    int tx = threadIdx.x & 15;      // b-quad
    int ty = threadIdx.x >> 4;      // hp-quad, 0..15
    float acc[4][4];
#pragma unroll
    for (int j = 0; j < 4; ++j)
#pragma unroll
        for (int i = 0; i < 4; ++i) acc[j][i] = 0.f;

    for (int k = 0; k < 128; ++k) {
        float4 a = *reinterpret_cast<const float4*>(&xS[k * PIN_PAD + tx * 4]);
        float4 w = *reinterpret_cast<const float4*>(&wS[k * PIN_PAD + ty * 4]);
        float aa[4] = {a.x, a.y, a.z, a.w};
        float ww[4] = {w.x, w.y, w.z, w.w};
#pragma unroll
        for (int j = 0; j < 4; ++j)
#pragma unroll
            for (int i = 0; i < 4; ++i)
                acc[j][i] = fmaf(ww[j], aa[i], acc[j][i]);
    }
#pragma unroll
    for (int j = 0; j < 4; ++j) {
        int hp = hp0 + ty * 4 + j;
        *reinterpret_cast<float4*>(&g_Iin[(t * NIN_ROWS + hp) * NB + tx * 4]) =
            make_float4(acc[j][0], acc[j][1], acc[j][2], acc[j][3]);
    }
}

// ---------------------------------------------------------------------------
// Persistent kernel: all 32 steps, weights resident in SMEM, 2 chunks/CTA.
// ---------------------------------------------------------------------------
__global__ void __launch_bounds__(128) persist(const float* __restrict__ b_rec,
                                               float* __restrict__ out) {
    extern __shared__ float sm[];
    const int bid = blockIdx.x;

    int tile = 0;
#pragma unroll
    for (int t = 1; t < NTILE; ++t)
        if (bid >= cBase[t]) tile = t;
    const int slot  = bid - cBase[tile];
    const int S     = cS[tile];
    const int tbase = cBase[tile];
    const int area  = cArea[tile];
    const int h0    = tile * 128;

    const int aE0 = (area > 0 ? area - 1 : 0);
    const int aE1 = (area < 3 ? area + 1 : 3);
    const int k0E = aE0 * EPER;
    const int lenE = (aE1 - aE0 + 1) * EPER;
    const int k0I = ESZ + area * IPER;
    const int cb = slot * 2;                   // exactly 2 chunks per CTA

    const int tid = threadIdx.x;
    const int tx = tid & 7;                    // b-group (8 b)
    const int ty = tid >> 3;                   // h-group (8 h), 0..15

    unsigned wS_u   = (unsigned)__cvta_generic_to_shared(sm);              // 2 x 16KB
    unsigned actS_u = (unsigned)__cvta_generic_to_shared(sm + 2 * 4096);   // 2 x 8KB

    auto kgOf = [&](int c) {
        int off = c * 32;
        return (off < lenE) ? (k0E + off) : (k0I + (off - lenE));
    };

    // ---- load this CTA's 2 weight chunks ONCE ----
#pragma unroll
    for (int ci = 0; ci < 2; ++ci) {
        int kg = kgOf(cb + ci);
        unsigned wB = wS_u + ci * 16384;
#pragma unroll
        for (int r = 0; r < 8; ++r) {
            int u = tid + r * 128;
            int kk = u >> 5, col = u & 31;
            cp16(wB + u * 16, g_WeffT + (kg + kk) * H + h0 + col * 4);
        }
    }
    cpcommit(); cpwait<0>(); __syncthreads();

    const int kg0 = kgOf(cb), kg1 = kgOf(cb + 1);

    // update-phase row range for this slot
    const int rlo = (slot * 128) / S, rhi = ((slot + 1) * 128) / S;
    const int rr = tid >> 4;                   // 0..7
    const int bq = tid & 15;                   // b-quad

    auto compute = [&](unsigned aB, unsigned wB, unsigned long long acc[8][4]) {
#pragma unroll
        for (int k = 0; k < 32; ++k) {
            unsigned long long a0, a1, a2, a3;
            unsigned aaddr = aB + k * 256 + tx * 32;
            asm volatile("ld.shared.v2.b64 {%0,%1}, [%2];"
                         : "=l"(a0), "=l"(a1) : "r"(aaddr));
            asm volatile("ld.shared.v2.b64 {%0,%1}, [%2+16];"
                         : "=l"(a2), "=l"(a3) : "r"(aaddr));
            float w0, w1, w2, w3, w4, w5, w6, w7;
            unsigned waddr = wB + k * 512 + ty * 32;
            asm volatile("ld.shared.v4.f32 {%0,%1,%2,%3}, [%4];"
                         : "=f"(w0), "=f"(w1), "=f"(w2), "=f"(w3) : "r"(waddr));
            asm volatile("ld.shared.v4.f32 {%0,%1,%2,%3}, [%4+16];"
                         : "=f"(w4), "=f"(w5), "=f"(w6), "=f"(w7) : "r"(waddr));
            unsigned long long d0 = dup2(w0), d1 = dup2(w1), d2 = dup2(w2), d3 = dup2(w3);
            unsigned long long d4 = dup2(w4), d5 = dup2(w5), d6 = dup2(w6), d7 = dup2(w7);
            ffma2(acc[0][0], a0, d0); ffma2(acc[0][1], a1, d0);
            ffma2(acc[0][2], a2, d0); ffma2(acc[0][3], a3, d0);
            ffma2(acc[1][0], a0, d1); ffma2(acc[1][1], a1, d1);
            ffma2(acc[1][2], a2, d1); ffma2(acc[1][3], a3, d1);
            ffma2(acc[2][0], a0, d2); ffma2(acc[2][1], a1, d2);
            ffma2(acc[2][2], a2, d2); ffma2(acc[2][3], a3, d2);
            ffma2(acc[3][0], a0, d3); ffma2(acc[3][1], a1, d3);
            ffma2(acc[3][2], a2, d3); ffma2(acc[3][3], a3, d3);
            ffma2(acc[4][0], a0, d4); ffma2(acc[4][1], a1, d4);
            ffma2(acc[4][2], a2, d4); ffma2(acc[4][3], a3, d4);
            ffma2(acc[5][0], a0, d5); ffma2(acc[5][1], a1, d5);
            ffma2(acc[5][2], a2, d5); ffma2(acc[5][3], a3, d5);
            ffma2(acc[6][0], a0, d6); ffma2(acc[6][1], a1, d6);
            ffma2(acc[6][2], a2, d6); ffma2(acc[6][3], a3, d6);
            ffma2(acc[7][0], a0, d7); ffma2(acc[7][1], a1, d7);
            ffma2(acc[7][2], a2, d7); ffma2(acc[7][3], a3, d7);
        }
    };

    auto issueA = [&](int kg, int buf) {
        unsigned aB = actS_u + buf * 8192;
        const float* asrc = g_actT + kg * 64;
#pragma unroll
        for (int r = 0; r < 4; ++r) {
            int u = tid + r * 128;
            cp16(aB + u * 16, asrc + u * 4);
        }
    };

    unsigned ep = 0;
    for (int t = 0; t < NT; ++t) {
        unsigned long long acc[8][4];
#pragma unroll
        for (int j = 0; j < 8; ++j)
#pragma unroll
            for (int p = 0; p < 4; ++p) acc[j][p] = 0ull;

        issueA(kg0, 0); cpcommit();
        issueA(kg1, 1); cpcommit();
        cpwait<1>(); __syncthreads();
        compute(actS_u, wS_u, acc);
        cpwait<0>(); __syncthreads();
        compute(actS_u + 8192, wS_u + 16384, acc);

        // write partials
#pragma unroll
        for (int j = 0; j < 8; ++j) {
            int hl = ty * 8 + j;
            UF2 u0, u1, u2, u3;
            u0.u = acc[j][0]; u1.u = acc[j][1]; u2.u = acc[j][2]; u3.u = acc[j][3];
            float* dst = g_P + (bid * 128 + hl) * NB + tx * 8;
            *reinterpret_cast<float4*>(dst)     = make_float4(u0.f.x, u0.f.y, u1.f.x, u1.f.y);
            *reinterpret_cast<float4*>(dst + 4) = make_float4(u2.f.x, u2.f.y, u3.f.x, u3.f.y);
        }

        gbar(bid, ++ep);

        // ---- fused update phase: rows [rlo, rhi) of this tile ----
        for (int r = rlo + rr; r < rhi; r += 8) {
            int h = h0 + r;
            float4 p = make_float4(0.f, 0.f, 0.f, 0.f);
            for (int s = 0; s < S; ++s) {
                float4 v = *reinterpret_cast<const float4*>(
                    &g_P[((tbase + s) * 128 + r) * NB + bq * 4]);
                p.x += v.x; p.y += v.y; p.z += v.z; p.w += v.w;
            }
            float br = b_rec[h];
            p.x += br; p.y += br; p.z += br; p.w += br;
            if (h < EPER || (h >= ESZ && h < ESZ + IPER)) {
                int hp = (h < EPER) ? h : (EPER + (h - ESZ));
                float4 iv = *reinterpret_cast<const float4*>(
                    &g_Iin[(t * NIN_ROWS + hp) * NB + bq * 4]);
                p.x += iv.x; p.y += iv.y; p.z += iv.z; p.w += iv.w;
            }
            float4 st = *reinterpret_cast<const float4*>(&g_state[h * NB + bq * 4]);
            float4 ns;
            ns.x = st.x * 0.8f + 0.2f * p.x;
            ns.y = st.y * 0.8f + 0.2f * p.y;
            ns.z = st.z * 0.8f + 0.2f * p.z;
            ns.w = st.w * 0.8f + 0.2f * p.w;
            *reinterpret_cast<float4*>(&g_state[h * NB + bq * 4]) = ns;
            float4 a;
            a.x = tanhf(fmaxf(ns.x, 0.0f));
            a.y = tanhf(fmaxf(ns.y, 0.0f));
            a.z = tanhf(fmaxf(ns.z, 0.0f));
            a.w = tanhf(fmaxf(ns.w, 0.0f));
            *reinterpret_cast<float4*>(&g_actT[h * NB + bq * 4]) = a;
            out[(t * NB + bq * 4 + 0) * H + h] = a.x;
            out[(t * NB + bq * 4 + 1) * H + h] = a.y;
            out[(t * NB + bq * 4 + 2) * H + h] = a.z;
            out[(t * NB + bq * 4 + 3) * H + h] = a.w;
        }

        gbar(bid, ++ep);
    }
}

// ---------------------------------------------------------------------------
extern "C" void kernel_launch(void* const* d_in, const int* in_sizes, int n_in,
                              void* d_out, int out_size) {
    (void)in_sizes; (void)n_in; (void)out_size;
    const float* x      = (const float*)d_in[0];
    const float* W_in   = (const float*)d_in[1];
    const float* W_rec  = (const float*)d_in[2];
    const float* b_rec  = (const float*)d_in[3];
    const float* state0 = (const float*)d_in[4];
    float* out = (float*)d_out;

    cudaFuncSetAttribute(persist,
                         cudaFuncAttributeMaxDynamicSharedMemorySize, SMEM_BYTES);
    cudaFuncSetAttribute(prep_input,
                         cudaFuncAttributeMaxDynamicSharedMemorySize, PIN_SMEM);

    init_bar<<<1, 32>>>();
    prep_weights<<<dim3(H / 32, H / 32), 128>>>(W_rec);
    prep_state<<<(NB * H + 255) / 256, 256>>>(state0);
    prep_input<<<dim3(NIN_ROWS / 64, NT), 256, PIN_SMEM>>>(x, W_in);

    persist<<<NCTA, 128, SMEM_BYTES>>>(b_rec, out);
}

// round 10
// speedup vs baseline: 1.6594x; 1.0575x over previous
#include <cuda_runtime.h>
#include <math.h>

// Problem constants
#define H      2560
#define ESZ    2048
#define EPER   512
#define IPER   128
#define NB     64
#define NT     32
#define INSZ   128
#define NIN_ROWS 640
#define NTILE  20
#define NCTA   440
// smem: 2 weight chunks (2*4096 floats) + 2 act buffers (2*2048) = 48 KB
#define SMEM_FLOATS (2*4096 + 2*2048)
#define SMEM_BYTES  (SMEM_FLOATS * 4)

// Schedule: tiles of 128 h-rows. Tiles 0-15 E (area=tile/4), 16-19 I (area=tile-16).
// Areas 0,3 -> 36 K-chunks -> 18 slots (2 each); areas 1,2 -> 52 -> 26 slots (2 each).
__constant__ int cArea[NTILE] = {0,0,0,0, 1,1,1,1, 2,2,2,2, 3,3,3,3, 0,1,2,3};
__constant__ int cS[NTILE]    = {18,18,18,18, 26,26,26,26, 26,26,26,26, 18,18,18,18, 18,26,26,18};
__constant__ int cBase[NTILE] = {0,18,36,54, 72,98,124,150, 176,202,228,254, 280,298,316,334, 352,370,396,422};

// Scratch (device globals)
__device__ float g_P[NCTA * 128 * NB];         // partials [slot][h_local][b]
__device__ float g_Iin[NT * NIN_ROWS * NB];    // input drive [t][h'][b]
__device__ float g_state[H * NB];              // state [h][b]
__device__ float g_actT[H * NB];               // retanh(state) [h][b]
__device__ float g_xrelu[NT * INSZ * NB];      // relu(x) transposed [t][k][b]

// Sync state (replay-safe: cumulative epochs + base-read; counter self-resets)
__device__ unsigned g_cnt0 = 0;
__device__ unsigned g_epoch = 0;
__device__ unsigned g_tileP[NTILE] = {};

union UF2 { unsigned long long u; float2 f; };

__device__ __forceinline__ void ffma2(unsigned long long& d,
                                      unsigned long long a,
                                      unsigned long long b) {
    asm("fma.rn.f32x2 %0, %1, %2, %0;" : "+l"(d) : "l"(a), "l"(b));
}
__device__ __forceinline__ unsigned long long dup2(float w) {
    unsigned long long r;
    asm("mov.b64 %0, {%1, %1};" : "=l"(r) : "r"(__float_as_uint(w)));
    return r;
}
__device__ __forceinline__ void cp16(unsigned dst, const float* src) {
    asm volatile("cp.async.cg.shared.global [%0], [%1], 16;" :: "r"(dst), "l"(src));
}
__device__ __forceinline__ void cpcommit() {
    asm volatile("cp.async.commit_group;");
}
template<int N> __device__ __forceinline__ void cpwait() {
    asm volatile("cp.async.wait_group %0;" :: "n"(N));
}

// device-wide epoch barrier: single counter, no sleep, wrap-safe != spin.
__device__ __forceinline__ void gbar(unsigned target) {
    __syncthreads();
    if (threadIdx.x == 0) {
        __threadfence();
        if (atomicAdd(&g_cnt0, 1) == NCTA - 1) {
            atomicExch(&g_cnt0, 0);
            __threadfence();
            atomicAdd(&g_epoch, 1);
        }
        while (*(volatile unsigned*)&g_epoch != target) {}
        __threadfence();
    }
    __syncthreads();
}

// ---------------------------------------------------------------------------
// THE kernel: prologue (weights/state/xrelu/input-GEMM) + 32 steps.
// ---------------------------------------------------------------------------
__global__ void __launch_bounds__(128, 3) persist(
    const float* __restrict__ x,      // [32, 64, 128]
    const float* __restrict__ W_in,   // [2560, 128]
    const float* __restrict__ W_rec,  // [2560, 2560]
    const float* __restrict__ b_rec,  // [2560]
    const float* __restrict__ state0, // [64, 2560]
    float* __restrict__ out)          // [32, 64, 2560]
{
    extern __shared__ float sm[];
    const int bid = blockIdx.x;
    const int tid = threadIdx.x;

    int tile = 0;
#pragma unroll
    for (int t = 1; t < NTILE; ++t)
        if (bid >= cBase[t]) tile = t;
    const int slot  = bid - cBase[tile];
    const int S     = cS[tile];
    const int tbase = cBase[tile];
    const int area  = cArea[tile];
    const int h0    = tile * 128;

    const int aE0 = (area > 0 ? area - 1 : 0);
    const int aE1 = (area < 3 ? area + 1 : 3);
    const int k0E = aE0 * EPER;
    const int lenE = (aE1 - aE0 + 1) * EPER;
    const int k0I = ESZ + area * IPER;
    const int cb = slot * 2;                   // exactly 2 chunks per CTA

    const int tx = tid & 7;                    // b-group (8 b)
    const int ty = tid >> 3;                   // h-group (8 h), 0..15

    unsigned wS_u   = (unsigned)__cvta_generic_to_shared(sm);              // 2 x 16KB
    unsigned actS_u = (unsigned)__cvta_generic_to_shared(sm + 2 * 4096);   // 2 x 8KB

    auto kgOf = [&](int c) {
        int off = c * 32;
        return (off < lenE) ? (k0E + off) : (k0I + (off - lenE));
    };
    const int kg0 = kgOf(cb), kg1 = kgOf(cb + 1);

    // ---- replay-safe bases (read before ANY arrival can happen) ----
    __shared__ unsigned sBase[2];
    if (tid == 0) {
        sBase[0] = *(volatile unsigned*)&g_epoch;
        sBase[1] = *(volatile unsigned*)&g_tileP[tile];
    }
    __syncthreads();
    const unsigned epBase = sBase[0];
    const unsigned tpBase = sBase[1];

    // =======================================================================
    // PROLOGUE
    // =======================================================================
    // A) weights: load directly from W_rec, apply |.|*sign and zero diag,
    //    store to smem [k_local][h_local]. Chunk k-ranges are connected areas
    //    by construction, so the conn mask is implicit.
#pragma unroll
    for (int ci = 0; ci < 2; ++ci) {
        int kg = (ci == 0) ? kg0 : kg1;
        float* wSm = sm + ci * 4096;
#pragma unroll
        for (int r = 0; r < 8; ++r) {
            int idx = tid + r * 128;
            int i = idx >> 3, q = idx & 7;
            int k = kg + q * 4;
            float4 v = *reinterpret_cast<const float4*>(&W_rec[(h0 + i) * H + k]);
            float sgn = (k < ESZ) ? 1.0f : -1.0f;
            float a0 = fabsf(v.x) * sgn, a1 = fabsf(v.y) * sgn;
            float a2 = fabsf(v.z) * sgn, a3 = fabsf(v.w) * sgn;
            int hg = h0 + i;
            if (hg == k)     a0 = 0.0f;
            if (hg == k + 1) a1 = 0.0f;
            if (hg == k + 2) a2 = 0.0f;
            if (hg == k + 3) a3 = 0.0f;
            wSm[(q * 4 + 0) * 128 + i] = a0;
            wSm[(q * 4 + 1) * 128 + i] = a1;
            wSm[(q * 4 + 2) * 128 + i] = a2;
            wSm[(q * 4 + 3) * 128 + i] = a3;
        }
    }

    // B) state + initial activation
    for (int e = bid * 128 + tid; e < NB * H; e += NCTA * 128) {
        int b = e / H, h = e % H;
        float s = state0[e];
        g_state[h * NB + b] = s;
        g_actT[h * NB + b] = tanhf(fmaxf(s, 0.0f));
    }

    // C) relu(x) transposed to [t][k][b]
    for (int e = bid * 128 + tid; e < NT * NB * INSZ; e += NCTA * 128) {
        int t = e >> 13;
        int r = e & 8191;
        int b = r >> 7, k = r & 127;
        g_xrelu[(t << 13) + k * 64 + b] = fmaxf(x[e], 0.0f);
    }

    gbar(epBase + 1);   // xrelu ready before input-GEMM pieces

    // D) input GEMM: Iin[t][hp][b] = sum_k xrelu[t][k][b] * |W_in[h(hp)][k]|
    //    1280 pieces (32 t x 40 hp-tiles of 16 rows), round-robin over CTAs.
    {
        float* smW = sm + 2 * 4096;   // reuse act-buffer region (8 KB)
        for (int p = bid; p < NT * 40; p += NCTA) {
            int t = p / 40, g = p % 40;
            int hp0 = g * 16;
            __syncthreads();
            for (int r2 = tid; r2 < 16 * 128; r2 += 128) {
                int row = r2 >> 7, kk = r2 & 127;
                int hp = hp0 + row;
                int h = (hp < EPER) ? hp : (ESZ + (hp - EPER));
                smW[row * 128 + kk] = fabsf(W_in[h * INSZ + kk]);
            }
            __syncthreads();
            int row = tid >> 3, bo = tid & 7;
            float acc0[4] = {0.f, 0.f, 0.f, 0.f}, acc1[4] = {0.f, 0.f, 0.f, 0.f};
            const float* xr = g_xrelu + (t << 13);
            for (int k = 0; k < 128; ++k) {
                float w = smW[row * 128 + k];
                float4 xa = *reinterpret_cast<const float4*>(&xr[k * 64 + bo * 8]);
                float4 xb = *reinterpret_cast<const float4*>(&xr[k * 64 + bo * 8 + 4]);
                acc0[0] = fmaf(w, xa.x, acc0[0]); acc0[1] = fmaf(w, xa.y, acc0[1]);
                acc0[2] = fmaf(w, xa.z, acc0[2]); acc0[3] = fmaf(w, xa.w, acc0[3]);
                acc1[0] = fmaf(w, xb.x, acc1[0]); acc1[1] = fmaf(w, xb.y, acc1[1]);
                acc1[2] = fmaf(w, xb.z, acc1[2]); acc1[3] = fmaf(w, xb.w, acc1[3]);
            }
            int hp = hp0 + row;
            float* dst = &g_Iin[(t * NIN_ROWS + hp) * NB + bo * 8];
            *reinterpret_cast<float4*>(dst)     = make_float4(acc0[0], acc0[1], acc0[2], acc0[3]);
            *reinterpret_cast<float4*>(dst + 4) = make_float4(acc1[0], acc1[1], acc1[2], acc1[3]);
        }
    }

    gbar(epBase + 2);   // state/act/Iin/weights all ready

    // =======================================================================
    // 32 STEPS
    // =======================================================================
    const int rlo = (slot * 128) / S, rhi = ((slot + 1) * 128) / S;
    const int rr = tid >> 4;                   // 0..7
    const int bq = tid & 15;                   // b-quad

    auto compute = [&](unsigned aB, unsigned wB, unsigned long long acc[8][4]) {
#pragma unroll
        for (int k = 0; k < 32; ++k) {
            unsigned long long a0, a1, a2, a3;
            unsigned aaddr = aB + k * 256 + tx * 32;
            asm volatile("ld.shared.v2.b64 {%0,%1}, [%2];"
                         : "=l"(a0), "=l"(a1) : "r"(aaddr));
            asm volatile("ld.shared.v2.b64 {%0,%1}, [%2+16];"
                         : "=l"(a2), "=l"(a3) : "r"(aaddr));
            float w0, w1, w2, w3, w4, w5, w6, w7;
            unsigned waddr = wB + k * 512 + ty * 32;
            asm volatile("ld.shared.v4.f32 {%0,%1,%2,%3}, [%4];"
                         : "=f"(w0), "=f"(w1), "=f"(w2), "=f"(w3) : "r"(waddr));
            asm volatile("ld.shared.v4.f32 {%0,%1,%2,%3}, [%4+16];"
                         : "=f"(w4), "=f"(w5), "=f"(w6), "=f"(w7) : "r"(waddr));
            unsigned long long d0 = dup2(w0), d1 = dup2(w1), d2 = dup2(w2), d3 = dup2(w3);
            unsigned long long d4 = dup2(w4), d5 = dup2(w5), d6 = dup2(w6), d7 = dup2(w7);
            ffma2(acc[0][0], a0, d0); ffma2(acc[0][1], a1, d0);
            ffma2(acc[0][2], a2, d0); ffma2(acc[0][3], a3, d0);
            ffma2(acc[1][0], a0, d1); ffma2(acc[1][1], a1, d1);
            ffma2(acc[1][2], a2, d1); ffma2(acc[1][3], a3, d1);
            ffma2(acc[2][0], a0, d2); ffma2(acc[2][1], a1, d2);
            ffma2(acc[2][2], a2, d2); ffma2(acc[2][3], a3, d2);
            ffma2(acc[3][0], a0, d3); ffma2(acc[3][1], a1, d3);
            ffma2(acc[3][2], a2, d3); ffma2(acc[3][3], a3, d3);
            ffma2(acc[4][0], a0, d4); ffma2(acc[4][1], a1, d4);
            ffma2(acc[4][2], a2, d4); ffma2(acc[4][3], a3, d4);
            ffma2(acc[5][0], a0, d5); ffma2(acc[5][1], a1, d5);
            ffma2(acc[5][2], a2, d5); ffma2(acc[5][3], a3, d5);
            ffma2(acc[6][0], a0, d6); ffma2(acc[6][1], a1, d6);
            ffma2(acc[6][2], a2, d6); ffma2(acc[6][3], a3, d6);
            ffma2(acc[7][0], a0, d7); ffma2(acc[7][1], a1, d7);
            ffma2(acc[7][2], a2, d7); ffma2(acc[7][3], a3, d7);
        }
    };

    auto issueA = [&](int kg, int buf) {
        unsigned aB = actS_u + buf * 8192;
        const float* asrc = g_actT + kg * 64;
#pragma unroll
        for (int r = 0; r < 4; ++r) {
            int u = tid + r * 128;
            cp16(aB + u * 16, asrc + u * 4);
        }
    };

    for (int t = 0; t < NT; ++t) {
        unsigned long long acc[8][4];
#pragma unroll
        for (int j = 0; j < 8; ++j)
#pragma unroll
            for (int p = 0; p < 4; ++p) acc[j][p] = 0ull;

        issueA(kg0, 0); cpcommit();
        issueA(kg1, 1); cpcommit();
        cpwait<1>(); __syncthreads();
        compute(actS_u, wS_u, acc);
        cpwait<0>(); __syncthreads();
        compute(actS_u + 8192, wS_u + 16384, acc);

        // write partials
#pragma unroll
        for (int j = 0; j < 8; ++j) {
            int hl = ty * 8 + j;
            UF2 u0, u1, u2, u3;
            u0.u = acc[j][0]; u1.u = acc[j][1]; u2.u = acc[j][2]; u3.u = acc[j][3];
            float* dst = g_P + (bid * 128 + hl) * NB + tx * 8;
            *reinterpret_cast<float4*>(dst)     = make_float4(u0.f.x, u0.f.y, u1.f.x, u1.f.y);
            *reinterpret_cast<float4*>(dst + 4) = make_float4(u2.f.x, u2.f.y, u3.f.x, u3.f.y);
        }

        // group sync: wait only for this tile's S partial-writers
        __syncthreads();
        if (tid == 0) {
            __threadfence();
            atomicAdd(&g_tileP[tile], 1);
            unsigned need = tpBase + (unsigned)S * (unsigned)(t + 1);
            while (*(volatile unsigned*)&g_tileP[tile] != need) {}
            __threadfence();
        }
        __syncthreads();

        // ---- fused update phase: rows [rlo, rhi) of this tile ----
        for (int r = rlo + rr; r < rhi; r += 8) {
            int h = h0 + r;
            float4 p = make_float4(0.f, 0.f, 0.f, 0.f);
            for (int s = 0; s < S; ++s) {
                float4 v = *reinterpret_cast<const float4*>(
                    &g_P[((tbase + s) * 128 + r) * NB + bq * 4]);
                p.x += v.x; p.y += v.y; p.z += v.z; p.w += v.w;
            }
            float br = b_rec[h];
            p.x += br; p.y += br; p.z += br; p.w += br;
            if (h < EPER || (h >= ESZ && h < ESZ + IPER)) {
                int hp = (h < EPER) ? h : (EPER + (h - ESZ));
                float4 iv = *reinterpret_cast<const float4*>(
                    &g_Iin[(t * NIN_ROWS + hp) * NB + bq * 4]);
                p.x += iv.x; p.y += iv.y; p.z += iv.z; p.w += iv.w;
            }
            float4 st = *reinterpret_cast<const float4*>(&g_state[h * NB + bq * 4]);
            float4 ns;
            ns.x = st.x * 0.8f + 0.2f * p.x;
            ns.y = st.y * 0.8f + 0.2f * p.y;
            ns.z = st.z * 0.8f + 0.2f * p.z;
            ns.w = st.w * 0.8f + 0.2f * p.w;
            *reinterpret_cast<float4*>(&g_state[h * NB + bq * 4]) = ns;
            float4 a;
            a.x = tanhf(fmaxf(ns.x, 0.0f));
            a.y = tanhf(fmaxf(ns.y, 0.0f));
            a.z = tanhf(fmaxf(ns.z, 0.0f));
            a.w = tanhf(fmaxf(ns.w, 0.0f));
            *reinterpret_cast<float4*>(&g_actT[h * NB + bq * 4]) = a;
            out[(t * NB + bq * 4 + 0) * H + h] = a.x;
            out[(t * NB + bq * 4 + 1) * H + h] = a.y;
            out[(t * NB + bq * 4 + 2) * H + h] = a.z;
            out[(t * NB + bq * 4 + 3) * H + h] = a.w;
        }

        if (t + 1 < NT) gbar(epBase + 3 + t);   // acts ready for next step
    }
}

// ---------------------------------------------------------------------------
extern "C" void kernel_launch(void* const* d_in, const int* in_sizes, int n_in,
                              void* d_out, int out_size) {
    (void)in_sizes; (void)n_in; (void)out_size;
    const float* x      = (const float*)d_in[0];
    const float* W_in   = (const float*)d_in[1];
    const float* W_rec  = (const float*)d_in[2];
    const float* b_rec  = (const float*)d_in[3];
    const float* state0 = (const float*)d_in[4];
    float* out = (float*)d_out;

    cudaFuncSetAttribute(persist,
                         cudaFuncAttributeMaxDynamicSharedMemorySize, SMEM_BYTES);

    persist<<<NCTA, 128, SMEM_BYTES>>>(x, W_in, W_rec, b_rec, state0, out);
}

// round 11
// speedup vs baseline: 1.6881x; 1.0173x over previous
#include <cuda_runtime.h>
#include <math.h>

// Problem constants
#define H      2560
#define ESZ    2048
#define EPER   512
#define IPER   128
#define NB     64
#define NT     32
#define INSZ   128
#define NIN_ROWS 640
#define NTILE  20
#define NCTA   440
// smem: 2 weight chunks (2*4096 floats) + 2 act buffers (2*2048) = 48 KB
#define SMEM_FLOATS (2*4096 + 2*2048)
#define SMEM_BYTES  (SMEM_FLOATS * 4)

// Schedule: tiles of 128 h-rows. Tiles 0-15 E (area=tile/4), 16-19 I (area=tile-16).
__constant__ int cArea[NTILE] = {0,0,0,0, 1,1,1,1, 2,2,2,2, 3,3,3,3, 0,1,2,3};
__constant__ int cS[NTILE]    = {18,18,18,18, 26,26,26,26, 26,26,26,26, 18,18,18,18, 18,26,26,18};
__constant__ int cBase[NTILE] = {0,18,36,54, 72,98,124,150, 176,202,228,254, 280,298,316,334, 352,370,396,422};
// chunk-instances consuming each tile's act rows (sums to 880)
__constant__ int cUses[NTILE] = {40,40,40,40, 60,60,60,60, 60,60,60,60, 40,40,40,40, 20,20,20,20};

// Scratch (device globals)
__device__ float g_P[2 * NCTA * 128 * NB];     // partials, double-buffered by t&1
__device__ float g_Iin[NT * NIN_ROWS * NB];    // input drive [t][h'][b]
__device__ float g_state[H * NB];              // state [h][b]
__device__ float g_act[2 * H * NB];            // retanh(state), ping-pong by t&1
__device__ float g_xrelu[NT * INSZ * NB];      // relu(x) transposed [t][k][b]

// Sync state (cumulative; replay-safe via base reads)
__device__ unsigned g_cnt0 = 0;
__device__ unsigned g_epoch = 0;
__device__ unsigned g_tileP[NTILE] = {};
__device__ unsigned g_actReady[NTILE] = {};
__device__ unsigned g_consumed[NTILE] = {};

union UF2 { unsigned long long u; float2 f; };

__device__ __forceinline__ void ffma2(unsigned long long& d,
                                      unsigned long long a,
                                      unsigned long long b) {
    asm("fma.rn.f32x2 %0, %1, %2, %0;" : "+l"(d) : "l"(a), "l"(b));
}
__device__ __forceinline__ unsigned long long dup2(float w) {
    unsigned long long r;
    asm("mov.b64 %0, {%1, %1};" : "=l"(r) : "r"(__float_as_uint(w)));
    return r;
}
__device__ __forceinline__ void cp16(unsigned dst, const float* src) {
    asm volatile("cp.async.cg.shared.global [%0], [%1], 16;" :: "r"(dst), "l"(src));
}
__device__ __forceinline__ void cpcommit() {
    asm volatile("cp.async.commit_group;");
}
template<int N> __device__ __forceinline__ void cpwait() {
    asm volatile("cp.async.wait_group %0;" :: "n"(N));
}
__device__ __forceinline__ void spinGE(volatile unsigned* cnt, unsigned base, unsigned need) {
    while ((unsigned)(*cnt - base) < need) {}
}

// device-wide epoch barrier (prologue only)
__device__ __forceinline__ void gbar(unsigned target) {
    __syncthreads();
    if (threadIdx.x == 0) {
        __threadfence();
        if (atomicAdd(&g_cnt0, 1) == NCTA - 1) {
            atomicExch(&g_cnt0, 0);
            __threadfence();
            atomicAdd(&g_epoch, 1);
        }
        while (*(volatile unsigned*)&g_epoch != target) {}
        __threadfence();
    }
    __syncthreads();
}

// ---------------------------------------------------------------------------
__global__ void __launch_bounds__(128, 3) persist(
    const float* __restrict__ x,
    const float* __restrict__ W_in,
    const float* __restrict__ W_rec,
    const float* __restrict__ b_rec,
    const float* __restrict__ state0,
    float* __restrict__ out)
{
    extern __shared__ float sm[];
    const int bid = blockIdx.x;
    const int tid = threadIdx.x;

    int tile = 0;
#pragma unroll
    for (int t = 1; t < NTILE; ++t)
        if (bid >= cBase[t]) tile = t;
    const int slot  = bid - cBase[tile];
    const int S     = cS[tile];
    const int tbase = cBase[tile];
    const int area  = cArea[tile];
    const int h0    = tile * 128;

    const int aE0 = (area > 0 ? area - 1 : 0);
    const int aE1 = (area < 3 ? area + 1 : 3);
    const int k0E = aE0 * EPER;
    const int lenE = (aE1 - aE0 + 1) * EPER;
    const int k0I = ESZ + area * IPER;
    const int cb = slot * 2;

    const int tx = tid & 7;
    const int ty = tid >> 3;

    unsigned wS_u   = (unsigned)__cvta_generic_to_shared(sm);
    unsigned actS_u = (unsigned)__cvta_generic_to_shared(sm + 2 * 4096);

    auto kgOf = [&](int c) {
        int off = c * 32;
        return (off < lenE) ? (k0E + off) : (k0I + (off - lenE));
    };
    const int kg0 = kgOf(cb), kg1 = kgOf(cb + 1);
    const int srcT0 = kg0 >> 7, srcT1 = kg1 >> 7;
    const unsigned S0 = (unsigned)cS[srcT0], S1 = (unsigned)cS[srcT1];
    const unsigned myUses = (unsigned)cUses[tile];

    // ---- replay-safe base reads (before ANY arrival this launch) ----
    __shared__ unsigned sB[6];
    if (tid == 0) {
        sB[0] = *(volatile unsigned*)&g_epoch;
        sB[1] = *(volatile unsigned*)&g_tileP[tile];
        sB[2] = *(volatile unsigned*)&g_consumed[tile];
        sB[3] = *(volatile unsigned*)&g_actReady[srcT0];
        sB[4] = *(volatile unsigned*)&g_actReady[srcT1];
    }
    __syncthreads();
    const unsigned epBase = sB[0], tpBase = sB[1], coBase = sB[2];
    const unsigned arBase0 = sB[3], arBase1 = sB[4];

    // =======================================================================
    // PROLOGUE
    // =======================================================================
#pragma unroll
    for (int ci = 0; ci < 2; ++ci) {
        int kg = (ci == 0) ? kg0 : kg1;
        float* wSm = sm + ci * 4096;
#pragma unroll
        for (int r = 0; r < 8; ++r) {
            int idx = tid + r * 128;
            int i = idx >> 3, q = idx & 7;
            int k = kg + q * 4;
            float4 v = *reinterpret_cast<const float4*>(&W_rec[(h0 + i) * H + k]);
            float sgn = (k < ESZ) ? 1.0f : -1.0f;
            float a0 = fabsf(v.x) * sgn, a1 = fabsf(v.y) * sgn;
            float a2 = fabsf(v.z) * sgn, a3 = fabsf(v.w) * sgn;
            int hg = h0 + i;
            if (hg == k)     a0 = 0.0f;
            if (hg == k + 1) a1 = 0.0f;
            if (hg == k + 2) a2 = 0.0f;
            if (hg == k + 3) a3 = 0.0f;
            wSm[(q * 4 + 0) * 128 + i] = a0;
            wSm[(q * 4 + 1) * 128 + i] = a1;
            wSm[(q * 4 + 2) * 128 + i] = a2;
            wSm[(q * 4 + 3) * 128 + i] = a3;
        }
    }

    for (int e = bid * 128 + tid; e < NB * H; e += NCTA * 128) {
        int b = e / H, h = e % H;
        float s = state0[e];
        g_state[h * NB + b] = s;
        g_act[h * NB + b] = tanhf(fmaxf(s, 0.0f));   // buf0 for t=0
    }

    for (int e = bid * 128 + tid; e < NT * NB * INSZ; e += NCTA * 128) {
        int t = e >> 13;
        int r = e & 8191;
        int b = r >> 7, k = r & 127;
        g_xrelu[(t << 13) + k * 64 + b] = fmaxf(x[e], 0.0f);
    }

    gbar(epBase + 1);

    {
        float* smW = sm + 2 * 4096;
        for (int p = bid; p < NT * 40; p += NCTA) {
            int t = p / 40, g = p % 40;
            int hp0 = g * 16;
            __syncthreads();
            for (int r2 = tid; r2 < 16 * 128; r2 += 128) {
                int row = r2 >> 7, kk = r2 & 127;
                int hp = hp0 + row;
                int h = (hp < EPER) ? hp : (ESZ + (hp - EPER));
                smW[row * 128 + kk] = fabsf(W_in[h * INSZ + kk]);
            }
            __syncthreads();
            int row = tid >> 3, bo = tid & 7;
            float acc0[4] = {0.f, 0.f, 0.f, 0.f}, acc1[4] = {0.f, 0.f, 0.f, 0.f};
            const float* xr = g_xrelu + (t << 13);
            for (int k = 0; k < 128; ++k) {
                float w = smW[row * 128 + k];
                float4 xa = *reinterpret_cast<const float4*>(&xr[k * 64 + bo * 8]);
                float4 xb = *reinterpret_cast<const float4*>(&xr[k * 64 + bo * 8 + 4]);
                acc0[0] = fmaf(w, xa.x, acc0[0]); acc0[1] = fmaf(w, xa.y, acc0[1]);
                acc0[2] = fmaf(w, xa.z, acc0[2]); acc0[3] = fmaf(w, xa.w, acc0[3]);
                acc1[0] = fmaf(w, xb.x, acc1[0]); acc1[1] = fmaf(w, xb.y, acc1[1]);
                acc1[2] = fmaf(w, xb.z, acc1[2]); acc1[3] = fmaf(w, xb.w, acc1[3]);
            }
            int hp = hp0 + row;
            float* dst = &g_Iin[(t * NIN_ROWS + hp) * NB + bo * 8];
            *reinterpret_cast<float4*>(dst)     = make_float4(acc0[0], acc0[1], acc0[2], acc0[3]);
            *reinterpret_cast<float4*>(dst + 4) = make_float4(acc1[0], acc1[1], acc1[2], acc1[3]);
        }
    }

    gbar(epBase + 2);   // everything ready; counters quiescent until here

    // =======================================================================
    // 32 STEPS — point-to-point tile dataflow, no global barrier
    // =======================================================================
    const int rlo = (slot * 128) / S, rhi = ((slot + 1) * 128) / S;
    const int rr = tid >> 4;
    const int bq = tid & 15;

    auto compute = [&](unsigned aB, unsigned wB, unsigned long long acc[8][4]) {
#pragma unroll
        for (int k = 0; k < 32; ++k) {
            unsigned long long a0, a1, a2, a3;
            unsigned aaddr = aB + k * 256 + tx * 32;
            asm volatile("ld.shared.v2.b64 {%0,%1}, [%2];"
                         : "=l"(a0), "=l"(a1) : "r"(aaddr));
            asm volatile("ld.shared.v2.b64 {%0,%1}, [%2+16];"
                         : "=l"(a2), "=l"(a3) : "r"(aaddr));
            float w0, w1, w2, w3, w4, w5, w6, w7;
            unsigned waddr = wB + k * 512 + ty * 32;
            asm volatile("ld.shared.v4.f32 {%0,%1,%2,%3}, [%4];"
                         : "=f"(w0), "=f"(w1), "=f"(w2), "=f"(w3) : "r"(waddr));
            asm volatile("ld.shared.v4.f32 {%0,%1,%2,%3}, [%4+16];"
                         : "=f"(w4), "=f"(w5), "=f"(w6), "=f"(w7) : "r"(waddr));
            unsigned long long d0 = dup2(w0), d1 = dup2(w1), d2 = dup2(w2), d3 = dup2(w3);
            unsigned long long d4 = dup2(w4), d5 = dup2(w5), d6 = dup2(w6), d7 = dup2(w7);
            ffma2(acc[0][0], a0, d0); ffma2(acc[0][1], a1, d0);
            ffma2(acc[0][2], a2, d0); ffma2(acc[0][3], a3, d0);
            ffma2(acc[1][0], a0, d1); ffma2(acc[1][1], a1, d1);
            ffma2(acc[1][2], a2, d1); ffma2(acc[1][3], a3, d1);
            ffma2(acc[2][0], a0, d2); ffma2(acc[2][1], a1, d2);
            ffma2(acc[2][2], a2, d2); ffma2(acc[2][3], a3, d2);
            ffma2(acc[3][0], a0, d3); ffma2(acc[3][1], a1, d3);
            ffma2(acc[3][2], a2, d3); ffma2(acc[3][3], a3, d3);
            ffma2(acc[4][0], a0, d4); ffma2(acc[4][1], a1, d4);
            ffma2(acc[4][2], a2, d4); ffma2(acc[4][3], a3, d4);
            ffma2(acc[5][0], a0, d5); ffma2(acc[5][1], a1, d5);
            ffma2(acc[5][2], a2, d5); ffma2(acc[5][3], a3, d5);
            ffma2(acc[6][0], a0, d6); ffma2(acc[6][1], a1, d6);
            ffma2(acc[6][2], a2, d6); ffma2(acc[6][3], a3, d6);
            ffma2(acc[7][0], a0, d7); ffma2(acc[7][1], a1, d7);
            ffma2(acc[7][2], a2, d7); ffma2(acc[7][3], a3, d7);
        }
    };

    for (int t = 0; t < NT; ++t) {
        const float* actSrc = g_act + (t & 1) * (H * NB);
        float* actDst = g_act + ((t + 1) & 1) * (H * NB);
        float* Pbuf = g_P + (t & 1) * (NCTA * 128 * NB);

        // 1) wait for source tiles' acts (update of step t-1)
        if (t > 0) {
            if (tid == 0) {
                spinGE(&g_actReady[srcT0], arBase0, S0 * (unsigned)t);
                spinGE(&g_actReady[srcT1], arBase1, S1 * (unsigned)t);
                __threadfence();
            }
            __syncthreads();
        }

        // 2) stage acts + compute
        unsigned long long acc[8][4];
#pragma unroll
        for (int j = 0; j < 8; ++j)
#pragma unroll
            for (int p = 0; p < 4; ++p) acc[j][p] = 0ull;

        {
            const float* a0s = actSrc + kg0 * 64;
            const float* a1s = actSrc + kg1 * 64;
#pragma unroll
            for (int r = 0; r < 4; ++r) {
                int u = tid + r * 128;
                cp16(actS_u + u * 16, a0s + u * 4);
            }
            cpcommit();
#pragma unroll
            for (int r = 0; r < 4; ++r) {
                int u = tid + r * 128;
                cp16(actS_u + 8192 + u * 16, a1s + u * 4);
            }
            cpcommit();
        }
        cpwait<1>(); __syncthreads();
        compute(actS_u, wS_u, acc);
        cpwait<0>(); __syncthreads();
        // acts fully staged -> release the buffer for future overwrite
        if (tid == 0) {
            __threadfence();
            atomicAdd(&g_consumed[srcT0], 1);
            atomicAdd(&g_consumed[srcT1], 1);
        }
        compute(actS_u + 8192, wS_u + 16384, acc);

        // 3) write partials (parity buffer)
#pragma unroll
        for (int j = 0; j < 8; ++j) {
            int hl = ty * 8 + j;
            UF2 u0, u1, u2, u3;
            u0.u = acc[j][0]; u1.u = acc[j][1]; u2.u = acc[j][2]; u3.u = acc[j][3];
            float* dst = Pbuf + (bid * 128 + hl) * NB + tx * 8;
            *reinterpret_cast<float4*>(dst)     = make_float4(u0.f.x, u0.f.y, u1.f.x, u1.f.y);
            *reinterpret_cast<float4*>(dst + 4) = make_float4(u2.f.x, u2.f.y, u3.f.x, u3.f.y);
        }

        // 4) tile partial-sync + act-buffer WAR guard
        __syncthreads();
        if (tid == 0) {
            __threadfence();
            atomicAdd(&g_tileP[tile], 1);
            spinGE(&g_tileP[tile], tpBase, (unsigned)S * (unsigned)(t + 1));
            spinGE(&g_consumed[tile], coBase, myUses * (unsigned)t);
            __threadfence();
        }
        __syncthreads();

        // 5) update rows [rlo, rhi)
        for (int r = rlo + rr; r < rhi; r += 8) {
            int h = h0 + r;
            float4 p = make_float4(0.f, 0.f, 0.f, 0.f);
            for (int s = 0; s < S; ++s) {
                float4 v = *reinterpret_cast<const float4*>(
                    &Pbuf[((tbase + s) * 128 + r) * NB + bq * 4]);
                p.x += v.x; p.y += v.y; p.z += v.z; p.w += v.w;
            }
            float br = b_rec[h];
            p.x += br; p.y += br; p.z += br; p.w += br;
            if (h < EPER || (h >= ESZ && h < ESZ + IPER)) {
                int hp = (h < EPER) ? h : (EPER + (h - ESZ));
                float4 iv = *reinterpret_cast<const float4*>(
                    &g_Iin[(t * NIN_ROWS + hp) * NB + bq * 4]);
                p.x += iv.x; p.y += iv.y; p.z += iv.z; p.w += iv.w;
            }
            float4 st = *reinterpret_cast<const float4*>(&g_state[h * NB + bq * 4]);
            float4 ns;
            ns.x = st.x * 0.8f + 0.2f * p.x;
            ns.y = st.y * 0.8f + 0.2f * p.y;
            ns.z = st.z * 0.8f + 0.2f * p.z;
            ns.w = st.w * 0.8f + 0.2f * p.w;
            *reinterpret_cast<float4*>(&g_state[h * NB + bq * 4]) = ns;
            float4 a;
            a.x = tanhf(fmaxf(ns.x, 0.0f));
            a.y = tanhf(fmaxf(ns.y, 0.0f));
            a.z = tanhf(fmaxf(ns.z, 0.0f));
            a.w = tanhf(fmaxf(ns.w, 0.0f));
            *reinterpret_cast<float4*>(&actDst[h * NB + bq * 4]) = a;
            out[(t * NB + bq * 4 + 0) * H + h] = a.x;
            out[(t * NB + bq * 4 + 1) * H + h] = a.y;
            out[(t * NB + bq * 4 + 2) * H + h] = a.z;
            out[(t * NB + bq * 4 + 3) * H + h] = a.w;
        }

        // 6) publish acts
        __syncthreads();
        if (tid == 0) {
            __threadfence();
            atomicAdd(&g_actReady[tile], 1);
        }
    }
}

// ---------------------------------------------------------------------------
extern "C" void kernel_launch(void* const* d_in, const int* in_sizes, int n_in,
                              void* d_out, int out_size) {
    (void)in_sizes; (void)n_in; (void)out_size;
    const float* x      = (const float*)d_in[0];
    const float* W_in   = (const float*)d_in[1];
    const float* W_rec  = (const float*)d_in[2];
    const float* b_rec  = (const float*)d_in[3];
    const float* state0 = (const float*)d_in[4];
    float* out = (float*)d_out;

    cudaFuncSetAttribute(persist,
                         cudaFuncAttributeMaxDynamicSharedMemorySize, SMEM_BYTES);

    persist<<<NCTA, 128, SMEM_BYTES>>>(x, W_in, W_rec, b_rec, state0, out);
}

// round 16
// speedup vs baseline: 2.0341x; 1.2050x over previous
#include <cuda_runtime.h>
#include <math.h>
#include <stdint.h>

// Problem constants
#define H      2560
#define ESZ    2048
#define EPER   512
#define IPER   128
#define NB     64
#define NT     32
#define INSZ   128
#define NIN_ROWS 640
#define NTILE  20
#define NCTA   440

// SMEM layout (bytes)
//  [1024..33792)   A f32, fragment-permuted: [mtile(8)][ks(8)][t(32)][slot(4)] (32 KB)
//  [33792..51200)  f32 act staging [64k][68b-padded]  (17408 B)
#define SM_A     1024
#define SM_F32   33792
#define BPAD     68
#define SMEM_BYTES 51200

// Schedule: 440 CTAs, 1 slab (64 k) per slot.
__constant__ int cArea[NTILE] = {0,0,0,0, 1,1,1,1, 2,2,2,2, 3,3,3,3, 0,1,2,3};
__constant__ int cS[NTILE]    = {18,18,18,18, 26,26,26,26, 26,26,26,26, 18,18,18,18, 18,26,26,18};
__constant__ int cBase[NTILE] = {0,18,36,54, 72,98,124,150, 176,202,228,254, 280,298,316,334, 352,370,396,422};
__constant__ int cUses[NTILE] = {20,20,20,20, 30,30,30,30, 30,30,30,30, 20,20,20,20, 10,10,10,10};

// Scratch (device globals)
__device__ float g_P[2 * NCTA * 128 * NB];
__device__ float g_Iin[NT * NIN_ROWS * NB];
__device__ float g_state[H * NB];
__device__ float g_act[2 * H * NB];
__device__ float g_xrelu[NT * INSZ * NB];

// Sync state (cumulative; replay-safe via base reads)
__device__ unsigned g_cnt0 = 0;
__device__ unsigned g_epoch = 0;
__device__ unsigned g_tileP[NTILE] = {};
__device__ unsigned g_actReady[NTILE] = {};
__device__ unsigned g_consumed[NTILE] = {};

__device__ __forceinline__ void cp16(unsigned dst, const float* src) {
    asm volatile("cp.async.cg.shared.global [%0], [%1], 16;" :: "r"(dst), "l"(src));
}
__device__ __forceinline__ void cpcommit() { asm volatile("cp.async.commit_group;"); }
template<int N> __device__ __forceinline__ void cpwait() {
    asm volatile("cp.async.wait_group %0;" :: "n"(N));
}
__device__ __forceinline__ void spinGE(volatile unsigned* cnt, unsigned base, unsigned need) {
    while ((unsigned)(*cnt - base) < need) {}
}
__device__ __forceinline__ uint32_t totf32(float x) {
    uint32_t r;
    asm("cvt.rna.tf32.f32 %0, %1;" : "=r"(r) : "f"(x));
    return r;
}
__device__ __forceinline__ void splittf(float x, uint32_t& hi, uint32_t& lo) {
    hi = totf32(x);
    lo = totf32(x - __uint_as_float(hi));
}
__device__ __forceinline__ void mmatf32(float d[4], const uint32_t a[4],
                                        uint32_t b0, uint32_t b1) {
    asm volatile(
        "mma.sync.aligned.m16n8k8.row.col.f32.tf32.tf32.f32 "
        "{%0,%1,%2,%3}, {%4,%5,%6,%7}, {%8,%9}, {%0,%1,%2,%3};"
        : "+f"(d[0]), "+f"(d[1]), "+f"(d[2]), "+f"(d[3])
        : "r"(a[0]), "r"(a[1]), "r"(a[2]), "r"(a[3]), "r"(b0), "r"(b1));
}

// device-wide epoch barrier (prologue only)
__device__ __forceinline__ void gbar(unsigned target) {
    __syncthreads();
    if (threadIdx.x == 0) {
        __threadfence();
        if (atomicAdd(&g_cnt0, 1) == NCTA - 1) {
            atomicExch(&g_cnt0, 0);
            __threadfence();
            atomicAdd(&g_epoch, 1);
        }
        while (*(volatile unsigned*)&g_epoch != target) {}
        __threadfence();
    }
    __syncthreads();
}

// ---------------------------------------------------------------------------
__global__ void __launch_bounds__(128, 3) persist(
    const float* __restrict__ x,
    const float* __restrict__ W_in,
    const float* __restrict__ W_rec,
    const float* __restrict__ b_rec,
    const float* __restrict__ state0,
    float* __restrict__ out)
{
    extern __shared__ float sm[];
    const int bid = blockIdx.x;
    const int tid = threadIdx.x;
    const int w = tid >> 5;
    const int l = tid & 31;
    const unsigned smb = (unsigned)__cvta_generic_to_shared(sm);
    const unsigned F_u = smb + SM_F32;
    float* smA = sm + SM_A / 4;         // fragment-permuted A (f32)
    float* fS  = sm + SM_F32 / 4;       // staging [64k][BPAD]

    int tile = 0;
#pragma unroll
    for (int t = 1; t < NTILE; ++t)
        if (bid >= cBase[t]) tile = t;
    const int slot  = bid - cBase[tile];
    const int S     = cS[tile];
    const int tbase = cBase[tile];
    const int area  = cArea[tile];
    const int h0    = tile * 128;

    const int aE0 = (area > 0 ? area - 1 : 0);
    const int aE1 = (area < 3 ? area + 1 : 3);
    const int k0E = aE0 * EPER;
    const int lenE = (aE1 - aE0 + 1) * EPER;
    const int k0I = ESZ + area * IPER;

    const int off = slot * 64;
    const int kg  = (off < lenE) ? (k0E + off) : (k0I + (off - lenE));
    const int srcT = kg >> 7;
    const unsigned Ssrc = (unsigned)cS[srcT];
    const unsigned myUses = (unsigned)cUses[tile];

    __shared__ unsigned sB[4];
    if (tid == 0) {
        sB[0] = *(volatile unsigned*)&g_epoch;
        sB[1] = *(volatile unsigned*)&g_tileP[tile];
        sB[2] = *(volatile unsigned*)&g_consumed[tile];
        sB[3] = *(volatile unsigned*)&g_actReady[srcT];
    }
    __syncthreads();
    const unsigned epBase = sB[0], tpBase = sB[1], coBase = sB[2], arBase = sB[3];

    // =======================================================================
    // PROLOGUE
    // =======================================================================
    // A) weights -> masked f32, scattered into mma fragment layout:
    //    value A[i][kl] -> smA[((mtile*8+ks)*32 + t)*4 + slot]
    //    mtile=i/16, r=i%16, ks=kl/8, kk=kl%8,
    //    t=(r%8)*4+(kk%4), slot=(r/8)+((kk/4)*2)
    {
        int i = tid;
        int hg = h0 + i;
        float sgn = (kg < ESZ) ? 1.0f : -1.0f;
        const float* wr = W_rec + (size_t)hg * H + kg;
        int mtile = i >> 4, r = i & 15;
#pragma unroll
        for (int q = 0; q < 16; ++q) {
            float4 v = *reinterpret_cast<const float4*>(wr + q * 4);
            float av[4] = {fabsf(v.x) * sgn, fabsf(v.y) * sgn,
                           fabsf(v.z) * sgn, fabsf(v.w) * sgn};
#pragma unroll
            for (int e = 0; e < 4; ++e) {
                int kl = q * 4 + e;
                if (hg == kg + kl) av[e] = 0.0f;
                int ks = kl >> 3, kk = kl & 7;
                int t2 = (r & 7) * 4 + (kk & 3);
                int sl = (r >> 3) + ((kk >> 2) << 1);
                smA[(((mtile * 8 + ks) * 32 + t2) << 2) + sl] = av[e];
            }
        }
    }

    // B) state + initial activation (f32 buf0)
    for (int e = bid * 128 + tid; e < NB * H; e += NCTA * 128) {
        int b = e / H, h = e % H;
        float s = state0[e];
        g_state[h * NB + b] = s;
        g_act[h * NB + b] = tanhf(fmaxf(s, 0.0f));
    }

    // C) relu(x) transposed to [t][k][b]
    for (int e = bid * 128 + tid; e < NT * NB * INSZ; e += NCTA * 128) {
        int t = e >> 13;
        int r = e & 8191;
        int b = r >> 7, k = r & 127;
        g_xrelu[(t << 13) + k * 64 + b] = fmaxf(x[e], 0.0f);
    }

    gbar(epBase + 1);

    // D) input GEMM (f32; uses staging region as weight smem)
    {
        float* smW = fS;
        for (int p = bid; p < NT * 40; p += NCTA) {
            int t = p / 40, g = p % 40;
            int hp0 = g * 16;
            __syncthreads();
            for (int r2 = tid; r2 < 16 * 128; r2 += 128) {
                int row = r2 >> 7, kk = r2 & 127;
                int hp = hp0 + row;
                int h = (hp < EPER) ? hp : (ESZ + (hp - EPER));
                smW[row * 128 + kk] = fabsf(W_in[h * INSZ + kk]);
            }
            __syncthreads();
            int row = tid >> 3, bo = tid & 7;
            float acc0[4] = {0.f, 0.f, 0.f, 0.f}, acc1[4] = {0.f, 0.f, 0.f, 0.f};
            const float* xr = g_xrelu + (t << 13);
            for (int k = 0; k < 128; ++k) {
                float wv = smW[row * 128 + k];
                float4 xa = *reinterpret_cast<const float4*>(&xr[k * 64 + bo * 8]);
                float4 xb = *reinterpret_cast<const float4*>(&xr[k * 64 + bo * 8 + 4]);
                acc0[0] = fmaf(wv, xa.x, acc0[0]); acc0[1] = fmaf(wv, xa.y, acc0[1]);
                acc0[2] = fmaf(wv, xa.z, acc0[2]); acc0[3] = fmaf(wv, xa.w, acc0[3]);
                acc1[0] = fmaf(wv, xb.x, acc1[0]); acc1[1] = fmaf(wv, xb.y, acc1[1]);
                acc1[2] = fmaf(wv, xb.z, acc1[2]); acc1[3] = fmaf(wv, xb.w, acc1[3]);
            }
            int hp = hp0 + row;
            float* dst = &g_Iin[(t * NIN_ROWS + hp) * NB + bo * 8];
            *reinterpret_cast<float4*>(dst)     = make_float4(acc0[0], acc0[1], acc0[2], acc0[3]);
            *reinterpret_cast<float4*>(dst + 4) = make_float4(acc1[0], acc1[1], acc1[2], acc1[3]);
        }
        __syncthreads();
    }

    gbar(epBase + 2);

    // =======================================================================
    // 32 STEPS
    // =======================================================================
    const int rlo = (slot * 128) / S, rhi = ((slot + 1) * 128) / S;
    const int rr = tid >> 4;
    const int bq = tid & 15;

    for (int t = 0; t < NT; ++t) {
        const float* actSrc = g_act + (t & 1) * (H * NB);
        float* actDst = g_act + ((t + 1) & 1) * (H * NB);
        float* Pbuf = g_P + (t & 1) * (NCTA * 128 * NB);

        // 1) wait for source tile acts
        if (t > 0) {
            if (tid == 0) {
                spinGE(&g_actReady[srcT], arBase, Ssrc * (unsigned)t);
                __threadfence();
            }
            __syncthreads();
        }

        // 2) stage f32 acts [64k][BPAD b] — BPAD=68 keeps every 16B cp dst aligned
        {
            const float* src = actSrc + (size_t)kg * 64;
#pragma unroll
            for (int r = 0; r < 8; ++r) {
                int u = tid + r * 128;          // 16B unit; floats u*4..u*4+3
                int row = u >> 4, col = (u & 15) * 4;
                cp16(F_u + (unsigned)(row * BPAD + col) * 4, src + u * 4);
            }
            cpcommit(); cpwait<0>(); __syncthreads();
        }
        if (tid == 0) { __threadfence(); atomicAdd(&g_consumed[srcT], 1); }

        // 3) MMA: tf32 2-term split. Warp w: h rows [w*32, w*32+32) x 64 b.
        float acc[2][8][4];
#pragma unroll
        for (int mt = 0; mt < 2; ++mt)
#pragma unroll
            for (int ng = 0; ng < 8; ++ng)
#pragma unroll
                for (int p = 0; p < 4; ++p) acc[mt][ng][p] = 0.f;

#pragma unroll
        for (int ks = 0; ks < 8; ++ks) {
            uint32_t ah[2][4], al[2][4];
#pragma unroll
            for (int mt = 0; mt < 2; ++mt) {
                float4 a4 = *reinterpret_cast<const float4*>(
                    &smA[(((2 * w + mt) * 8 + ks) * 32 + l) << 2]);
                splittf(a4.x, ah[mt][0], al[mt][0]);
                splittf(a4.y, ah[mt][1], al[mt][1]);
                splittf(a4.z, ah[mt][2], al[mt][2]);
                splittf(a4.w, ah[mt][3], al[mt][3]);
            }
#pragma unroll
            for (int ng = 0; ng < 8; ++ng) {
                float b0f = fS[(ks * 8 + (l & 3)) * BPAD + ng * 8 + (l >> 2)];
                float b1f = fS[(ks * 8 + 4 + (l & 3)) * BPAD + ng * 8 + (l >> 2)];
                uint32_t bh0, bl0, bh1, bl1;
                splittf(b0f, bh0, bl0);
                splittf(b1f, bh1, bl1);
#pragma unroll
                for (int mt = 0; mt < 2; ++mt) {
                    mmatf32(acc[mt][ng], ah[mt], bh0, bh1);
                    mmatf32(acc[mt][ng], ah[mt], bl0, bl1);
                    mmatf32(acc[mt][ng], al[mt], bh0, bh1);
                }
            }
        }

        // 4) write partials: D map r=(l/4, l/4+8), c=(l%4)*2 within ng*8
        {
            int r0 = l >> 2, c0 = (l & 3) * 2;
#pragma unroll
            for (int mt = 0; mt < 2; ++mt) {
                int hb = bid * 128 + w * 32 + mt * 16;
                float* p0 = Pbuf + (size_t)(hb + r0) * NB;
                float* p1 = Pbuf + (size_t)(hb + r0 + 8) * NB;
#pragma unroll
                for (int ng = 0; ng < 8; ++ng) {
                    *reinterpret_cast<float2*>(p0 + ng * 8 + c0) =
                        make_float2(acc[mt][ng][0], acc[mt][ng][1]);
                    *reinterpret_cast<float2*>(p1 + ng * 8 + c0) =
                        make_float2(acc[mt][ng][2], acc[mt][ng][3]);
                }
            }
        }

        // 5) tile partial-sync + act-buffer WAR guard
        __syncthreads();
        if (tid == 0) {
            __threadfence();
            atomicAdd(&g_tileP[tile], 1);
            spinGE(&g_tileP[tile], tpBase, (unsigned)S * (unsigned)(t + 1));
            spinGE(&g_consumed[tile], coBase, myUses * (unsigned)t);
            __threadfence();
        }
        __syncthreads();

        // 6) update rows [rlo, rhi)
        for (int r = rlo + rr; r < rhi; r += 8) {
            int h = h0 + r;
            float4 p = make_float4(0.f, 0.f, 0.f, 0.f);
            for (int s = 0; s < S; ++s) {
                float4 v = *reinterpret_cast<const float4*>(
                    &Pbuf[((size_t)(tbase + s) * 128 + r) * NB + bq * 4]);
                p.x += v.x; p.y += v.y; p.z += v.z; p.w += v.w;
            }
            float br = b_rec[h];
            p.x += br; p.y += br; p.z += br; p.w += br;
            if (h < EPER || (h >= ESZ && h < ESZ + IPER)) {
                int hp = (h < EPER) ? h : (EPER + (h - ESZ));
                float4 iv = *reinterpret_cast<const float4*>(
                    &g_Iin[(t * NIN_ROWS + hp) * NB + bq * 4]);
                p.x += iv.x; p.y += iv.y; p.z += iv.z; p.w += iv.w;
            }
            float4 st = *reinterpret_cast<const float4*>(&g_state[h * NB + bq * 4]);
            float4 ns;
            ns.x = st.x * 0.8f + 0.2f * p.x;
            ns.y = st.y * 0.8f + 0.2f * p.y;
            ns.z = st.z * 0.8f + 0.2f * p.z;
            ns.w = st.w * 0.8f + 0.2f * p.w;
            *reinterpret_cast<float4*>(&g_state[h * NB + bq * 4]) = ns;
            float4 a;
            a.x = tanhf(fmaxf(ns.x, 0.0f));
            a.y = tanhf(fmaxf(ns.y, 0.0f));
            a.z = tanhf(fmaxf(ns.z, 0.0f));
            a.w = tanhf(fmaxf(ns.w, 0.0f));
            *reinterpret_cast<float4*>(&actDst[h * NB + bq * 4]) = a;
            out[(t * NB + bq * 4 + 0) * H + h] = a.x;
            out[(t * NB + bq * 4 + 1) * H + h] = a.y;
            out[(t * NB + bq * 4 + 2) * H + h] = a.z;
            out[(t * NB + bq * 4 + 3) * H + h] = a.w;
        }

        // 7) publish acts
        __syncthreads();
        if (tid == 0) { __threadfence(); atomicAdd(&g_actReady[tile], 1); }
    }
}

// ---------------------------------------------------------------------------
extern "C" void kernel_launch(void* const* d_in, const int* in_sizes, int n_in,
                              void* d_out, int out_size) {
    (void)in_sizes; (void)n_in; (void)out_size;
    const float* x      = (const float*)d_in[0];
    const float* W_in   = (const float*)d_in[1];
    const float* W_rec  = (const float*)d_in[2];
    const float* b_rec  = (const float*)d_in[3];
    const float* state0 = (const float*)d_in[4];
    float* out = (float*)d_out;

    cudaFuncSetAttribute(persist,
                         cudaFuncAttributeMaxDynamicSharedMemorySize, SMEM_BYTES);

    persist<<<NCTA, 128, SMEM_BYTES>>>(x, W_in, W_rec, b_rec, state0, out);
}